// round 1
// baseline (speedup 1.0000x reference)
#include <cuda_runtime.h>
#include <math.h>

// Problem constants
#define BB 4
#define SS 2048
#define DD 2048
#define HH 16
#define HD 128
#define F3D (3*DD)          // 6144
#define MROWS (BB*SS)       // 8192

// Scratch (device globals; no allocation allowed)
__device__ float g_win_n[F3D * DD];     // 6144x2048 normalized w_in
__device__ float g_wout_n[DD * DD];     // 2048x2048 normalized w_out
__device__ float g_qkv[(size_t)MROWS * F3D]; // 8192x6144
__device__ float g_a[(size_t)MROWS * DD];    // 8192x2048 (rms-normed attn out)

// ---------------------------------------------------------------------------
// Row unit-normalize: out[r,:] = w[r,:] * rsqrt(sum(w[r,:]^2) + 1e-6)
// one block (256 thr) per row, cols multiple of 1024
// ---------------------------------------------------------------------------
__global__ void __launch_bounds__(256) unit_norm_rows(
    const float* __restrict__ w, float* __restrict__ o, int cols)
{
    int row = blockIdx.x, tid = threadIdx.x;
    const float* src = w + (size_t)row * cols;
    float* dst = o + (size_t)row * cols;
    float ss = 0.f;
    for (int i = tid * 4; i < cols; i += 1024) {
        float4 v = *(const float4*)(src + i);
        ss += v.x*v.x + v.y*v.y + v.z*v.z + v.w*v.w;
    }
    #pragma unroll
    for (int off = 16; off; off >>= 1) ss += __shfl_xor_sync(0xffffffffu, ss, off);
    __shared__ float red[8];
    if ((tid & 31) == 0) red[tid >> 5] = ss;
    __syncthreads();
    float total = 0.f;
    #pragma unroll
    for (int i = 0; i < 8; i++) total += red[i];
    float r = rsqrtf(total + 1e-6f);
    for (int i = tid * 4; i < cols; i += 1024) {
        float4 v = *(const float4*)(src + i);
        v.x *= r; v.y *= r; v.z *= r; v.w *= r;
        *(float4*)(dst + i) = v;
    }
}

// ---------------------------------------------------------------------------
// SGEMM: C[m,n] = sum_k A[m,k] * B[n,k]   (A: MxK row-major, B: NxK row-major)
// BM=BN=128, BK=8, 256 threads, 8x8 microtile. All dims multiples of tiles.
// ---------------------------------------------------------------------------
__global__ void __launch_bounds__(256) sgemm_nt(
    const float* __restrict__ A, const float* __restrict__ B,
    float* __restrict__ C, int M, int N, int K)
{
    const int BM = 128, BN = 128, BK = 8;
    __shared__ float As[BK][BM];
    __shared__ float Bs[BK][BN];
    int tid = threadIdx.x;
    int mBase = blockIdx.y * BM, nBase = blockIdx.x * BN;

    int lr = tid >> 1;          // 0..127 (row within tile)
    int lc = (tid & 1) * 4;     // 0 or 4 (k offset)
    const float* Ap = A + (size_t)(mBase + lr) * K + lc;
    const float* Bp = B + (size_t)(nBase + lr) * K + lc;

    int tx = tid & 15, ty = tid >> 4;
    float acc[8][8];
    #pragma unroll
    for (int i = 0; i < 8; i++)
        #pragma unroll
        for (int j = 0; j < 8; j++) acc[i][j] = 0.f;

    for (int k0 = 0; k0 < K; k0 += BK) {
        float4 av = *(const float4*)(Ap + k0);
        float4 bv = *(const float4*)(Bp + k0);
        __syncthreads();
        As[lc+0][lr] = av.x; As[lc+1][lr] = av.y; As[lc+2][lr] = av.z; As[lc+3][lr] = av.w;
        Bs[lc+0][lr] = bv.x; Bs[lc+1][lr] = bv.y; Bs[lc+2][lr] = bv.z; Bs[lc+3][lr] = bv.w;
        __syncthreads();
        #pragma unroll
        for (int k = 0; k < BK; k++) {
            float4 a0 = *(const float4*)&As[k][ty * 8];
            float4 a1 = *(const float4*)&As[k][ty * 8 + 4];
            float4 b0 = *(const float4*)&Bs[k][tx * 8];
            float4 b1 = *(const float4*)&Bs[k][tx * 8 + 4];
            float a[8] = {a0.x,a0.y,a0.z,a0.w,a1.x,a1.y,a1.z,a1.w};
            float b[8] = {b0.x,b0.y,b0.z,b0.w,b1.x,b1.y,b1.z,b1.w};
            #pragma unroll
            for (int i = 0; i < 8; i++)
                #pragma unroll
                for (int j = 0; j < 8; j++)
                    acc[i][j] = fmaf(a[i], b[j], acc[i][j]);
        }
    }

    float* Cp = C + (size_t)(mBase + ty * 8) * N + nBase + tx * 8;
    #pragma unroll
    for (int i = 0; i < 8; i++) {
        float4 v0 = {acc[i][0], acc[i][1], acc[i][2], acc[i][3]};
        float4 v1 = {acc[i][4], acc[i][5], acc[i][6], acc[i][7]};
        *(float4*)(Cp + (size_t)i * N)     = v0;
        *(float4*)(Cp + (size_t)i * N + 4) = v1;
    }
}

// ---------------------------------------------------------------------------
// RMS-norm q and k rows in-place inside qkv: one warp per 128-elem row.
// total rows = B*S*H*2
// ---------------------------------------------------------------------------
__global__ void __launch_bounds__(256) rmsnorm_qk(float* __restrict__ qkv)
{
    int gw = (blockIdx.x * blockDim.x + threadIdx.x) >> 5;
    int lane = threadIdx.x & 31;
    const int total = BB * SS * HH * 2;
    if (gw >= total) return;
    int which = gw & 1;          // 0=q, 1=k
    int t = gw >> 1;
    int h = t % HH;
    int bs = t / HH;
    float* p = qkv + (size_t)bs * F3D + which * DD + h * HD + lane * 4;
    float4 v = *(float4*)p;
    float ss = v.x*v.x + v.y*v.y + v.z*v.z + v.w*v.w;
    #pragma unroll
    for (int off = 16; off; off >>= 1) ss += __shfl_xor_sync(0xffffffffu, ss, off);
    float r = rsqrtf(ss * (1.f / HD) + 1e-6f);
    v.x *= r; v.y *= r; v.z *= r; v.w *= r;
    *(float4*)p = v;
}

// ---------------------------------------------------------------------------
// Causal flash attention, fp32. BM=64 q-rows/block, BN=32 keys/iter, hd=128.
// 256 threads: row = tid/4 (64 rows), sub = tid%4 (32 dims each).
// Fused epilogue: o/l then rms_norm over the 128 head dims, write to g_a.
// ---------------------------------------------------------------------------
__global__ void __launch_bounds__(256) flash_attn(
    const float* __restrict__ qkv, float* __restrict__ out)
{
    const int BM = 64, BN = 32;
    __shared__ float Ks[BN][HD];
    __shared__ float Vs[BN][HD];

    int tid = threadIdx.x;
    int row = tid >> 2, sub = tid & 3;
    int b = blockIdx.z, h = blockIdx.y;
    int qIdx = blockIdx.x * BM + row;

    const float* qptr = qkv + ((size_t)(b * SS + qIdx)) * F3D + h * HD + sub * 32;
    float qf[32];
    #pragma unroll
    for (int i = 0; i < 32; i += 4) {
        float4 t = *(const float4*)(qptr + i);
        qf[i] = t.x; qf[i+1] = t.y; qf[i+2] = t.z; qf[i+3] = t.w;
    }

    float o[32];
    #pragma unroll
    for (int i = 0; i < 32; i++) o[i] = 0.f;
    float m = -INFINITY, l = 0.f;
    const float scale = 0.08838834764831845f;  // 1/sqrt(128)

    int kEnd = (blockIdx.x + 1) * BM;
    for (int k0 = 0; k0 < kEnd; k0 += BN) {
        __syncthreads();
        // load K,V tiles (32 rows x 32 float4)
        for (int i = tid; i < BN * 32; i += 256) {
            int r = i >> 5;
            int c4 = (i & 31) * 4;
            const float* kp = qkv + ((size_t)(b * SS + k0 + r)) * F3D + DD + h * HD + c4;
            *(float4*)&Ks[r][c4] = *(const float4*)kp;
            *(float4*)&Vs[r][c4] = *(const float4*)(kp + DD);
        }
        __syncthreads();

        float s[BN];
        #pragma unroll
        for (int n = 0; n < BN; n++) {
            float acc = 0.f;
            #pragma unroll
            for (int d = 0; d < 32; d += 4) {
                float4 kv = *(const float4*)&Ks[n][sub * 32 + d];
                acc = fmaf(qf[d],   kv.x, acc);
                acc = fmaf(qf[d+1], kv.y, acc);
                acc = fmaf(qf[d+2], kv.z, acc);
                acc = fmaf(qf[d+3], kv.w, acc);
            }
            acc += __shfl_xor_sync(0xffffffffu, acc, 1);
            acc += __shfl_xor_sync(0xffffffffu, acc, 2);
            s[n] = (k0 + n > qIdx) ? -INFINITY : acc * scale;
        }
        float mt = m;
        #pragma unroll
        for (int n = 0; n < BN; n++) mt = fmaxf(mt, s[n]);
        float corr = __expf(m - mt);
        m = mt;
        float psum = 0.f;
        #pragma unroll
        for (int n = 0; n < BN; n++) { s[n] = __expf(s[n] - mt); psum += s[n]; }
        l = l * corr + psum;
        #pragma unroll
        for (int d = 0; d < 32; d++) o[d] *= corr;
        #pragma unroll
        for (int n = 0; n < BN; n++) {
            float pn = s[n];
            #pragma unroll
            for (int d = 0; d < 32; d += 4) {
                float4 vv = *(const float4*)&Vs[n][sub * 32 + d];
                o[d]   = fmaf(pn, vv.x, o[d]);
                o[d+1] = fmaf(pn, vv.y, o[d+1]);
                o[d+2] = fmaf(pn, vv.z, o[d+2]);
                o[d+3] = fmaf(pn, vv.w, o[d+3]);
            }
        }
    }

    // finalize: softmax normalize, then rms_norm over 128 dims (4 subs x 32)
    float inv_l = 1.f / l;
    float ss = 0.f;
    #pragma unroll
    for (int d = 0; d < 32; d++) { o[d] *= inv_l; ss += o[d] * o[d]; }
    ss += __shfl_xor_sync(0xffffffffu, ss, 1);
    ss += __shfl_xor_sync(0xffffffffu, ss, 2);
    float r = rsqrtf(ss * (1.f / HD) + 1e-6f);
    float* op = out + ((size_t)(b * SS + qIdx)) * DD + h * HD + sub * 32;
    #pragma unroll
    for (int d = 0; d < 32; d += 4) {
        float4 t = {o[d] * r, o[d+1] * r, o[d+2] * r, o[d+3] * r};
        *(float4*)(op + d) = t;
    }
}

// ---------------------------------------------------------------------------
extern "C" void kernel_launch(void* const* d_in, const int* in_sizes, int n_in,
                              void* d_out, int out_size)
{
    // Map inputs by element count (x=16777216, w_in=12582912, w_out=4194304)
    const float* x = nullptr; const float* w_in = nullptr; const float* w_out = nullptr;
    for (int i = 0; i < n_in; i++) {
        if (in_sizes[i] == BB * SS * DD)      x     = (const float*)d_in[i];
        else if (in_sizes[i] == F3D * DD)     w_in  = (const float*)d_in[i];
        else if (in_sizes[i] == DD * DD)      w_out = (const float*)d_in[i];
    }

    float* win_n; cudaGetSymbolAddress((void**)&win_n, g_win_n);
    float* wout_n; cudaGetSymbolAddress((void**)&wout_n, g_wout_n);
    float* qkv; cudaGetSymbolAddress((void**)&qkv, g_qkv);
    float* a; cudaGetSymbolAddress((void**)&a, g_a);

    // 1) normalize weights
    unit_norm_rows<<<F3D, 256>>>(w_in, win_n, DD);
    unit_norm_rows<<<DD, 256>>>(w_out, wout_n, DD);

    // 2) qkv = x @ w_in_n^T : [8192,6144]
    {
        dim3 grid(F3D / 128, MROWS / 128);
        sgemm_nt<<<grid, 256>>>(x, win_n, qkv, MROWS, F3D, DD);
    }

    // 3) rms_norm q,k rows (in place)
    {
        int totalWarps = BB * SS * HH * 2;
        int blocks = (totalWarps * 32 + 255) / 256;
        rmsnorm_qk<<<blocks, 256>>>(qkv);
    }

    // 4) flash attention + fused rms_norm -> g_a [8192,2048]
    {
        dim3 grid(SS / 64, HH, BB);
        flash_attn<<<grid, 256>>>(qkv, a);
    }

    // 5) out = a @ w_out_n^T : [8192,2048]
    {
        dim3 grid(DD / 128, MROWS / 128);
        sgemm_nt<<<grid, 256>>>(a, wout_n, (float*)d_out, MROWS, DD, DD);
    }
}

// round 2
// speedup vs baseline: 1.3108x; 1.3108x over previous
#include <cuda_runtime.h>
#include <math.h>

// Problem constants
#define BB 4
#define SS 2048
#define DD 2048
#define HH 16
#define HD 128
#define F3D (3*DD)          // 6144
#define MROWS (BB*SS)       // 8192

// Scratch (device globals; no allocation allowed)
__device__ float g_win_n[F3D * DD];          // 6144x2048 normalized w_in
__device__ float g_wout_n[DD * DD];          // 2048x2048 normalized w_out
__device__ float g_qkv[(size_t)MROWS * F3D]; // 8192x6144
__device__ float g_a[(size_t)MROWS * DD];    // 8192x2048 (rms-normed attn out)

// ---------------------------------------------------------------------------
__device__ __forceinline__ unsigned f2tf32(float x) {
    unsigned u;
    asm("cvt.rna.tf32.f32 %0, %1;" : "=r"(u) : "f"(x));
    return u;
}

__device__ __forceinline__ void mma_tf32(float* c, const unsigned* a, const unsigned* b) {
    asm volatile(
        "mma.sync.aligned.m16n8k8.row.col.f32.tf32.tf32.f32 "
        "{%0,%1,%2,%3}, {%4,%5,%6,%7}, {%8,%9}, {%0,%1,%2,%3};"
        : "+f"(c[0]), "+f"(c[1]), "+f"(c[2]), "+f"(c[3])
        : "r"(a[0]), "r"(a[1]), "r"(a[2]), "r"(a[3]), "r"(b[0]), "r"(b[1]));
}

// ---------------------------------------------------------------------------
// Row unit-normalize: out[r,:] = w[r,:] * rsqrt(sum(w[r,:]^2) + 1e-6)
// ---------------------------------------------------------------------------
__global__ void __launch_bounds__(256) unit_norm_rows(
    const float* __restrict__ w, float* __restrict__ o, int cols)
{
    int row = blockIdx.x, tid = threadIdx.x;
    const float* src = w + (size_t)row * cols;
    float* dst = o + (size_t)row * cols;
    float ss = 0.f;
    for (int i = tid * 4; i < cols; i += 1024) {
        float4 v = *(const float4*)(src + i);
        ss += v.x*v.x + v.y*v.y + v.z*v.z + v.w*v.w;
    }
    #pragma unroll
    for (int off = 16; off; off >>= 1) ss += __shfl_xor_sync(0xffffffffu, ss, off);
    __shared__ float red[8];
    if ((tid & 31) == 0) red[tid >> 5] = ss;
    __syncthreads();
    float total = 0.f;
    #pragma unroll
    for (int i = 0; i < 8; i++) total += red[i];
    float r = rsqrtf(total + 1e-6f);
    for (int i = tid * 4; i < cols; i += 1024) {
        float4 v = *(const float4*)(src + i);
        v.x *= r; v.y *= r; v.z *= r; v.w *= r;
        *(float4*)(dst + i) = v;
    }
}

// ---------------------------------------------------------------------------
// TF32 tensor-core GEMM: C[m,n] = sum_k A[m,k] * B[n,k]
// A: MxK row-major, B: NxK row-major. BM=BN=128, BK=16, 256 thr, 8 warps
// warp tile 64x32 (2x4 warp grid), mma m16n8k8 (4 m-frags x 4 n-frags x 2 k)
// smem stride BK+4=20: conflict-free fragment loads.
// ---------------------------------------------------------------------------
#define BKP 20
__global__ void __launch_bounds__(256, 2) gemm_tf32(
    const float* __restrict__ A, const float* __restrict__ B,
    float* __restrict__ C, int M, int N, int K)
{
    __shared__ unsigned As[128 * BKP];
    __shared__ unsigned Bs[128 * BKP];

    int tid = threadIdx.x, lane = tid & 31, warp = tid >> 5;
    int wm = warp >> 2, wn = warp & 3;
    int mBase = blockIdx.y * 128, nBase = blockIdx.x * 128;

    // global load mapping: two float4 chunks per thread per tile
    int r0 = tid >> 2,        c40 = (tid & 3) * 4;          // rows 0..63
    int r1 = (tid + 256) >> 2, c41 = c40;                   // rows 64..127
    const float* Ap0 = A + (size_t)(mBase + r0) * K + c40;
    const float* Ap1 = A + (size_t)(mBase + r1) * K + c41;
    const float* Bp0 = B + (size_t)(nBase + r0) * K + c40;
    const float* Bp1 = B + (size_t)(nBase + r1) * K + c41;

    float acc[4][4][4];
    #pragma unroll
    for (int i = 0; i < 4; i++)
        #pragma unroll
        for (int j = 0; j < 4; j++)
            #pragma unroll
            for (int l = 0; l < 4; l++) acc[i][j][l] = 0.f;

    // prefetch tile 0
    float4 av0 = *(const float4*)Ap0;
    float4 av1 = *(const float4*)Ap1;
    float4 bv0 = *(const float4*)Bp0;
    float4 bv1 = *(const float4*)Bp1;

    int lr = lane >> 2;   // 0..7
    int lc = lane & 3;    // 0..3

    for (int k0 = 0; k0 < K; k0 += 16) {
        // stage current tile to smem (tf32-rounded)
        {
            uint4 u;
            u.x = f2tf32(av0.x); u.y = f2tf32(av0.y); u.z = f2tf32(av0.z); u.w = f2tf32(av0.w);
            *(uint4*)&As[r0 * BKP + c40] = u;
            u.x = f2tf32(av1.x); u.y = f2tf32(av1.y); u.z = f2tf32(av1.z); u.w = f2tf32(av1.w);
            *(uint4*)&As[r1 * BKP + c41] = u;
            u.x = f2tf32(bv0.x); u.y = f2tf32(bv0.y); u.z = f2tf32(bv0.z); u.w = f2tf32(bv0.w);
            *(uint4*)&Bs[r0 * BKP + c40] = u;
            u.x = f2tf32(bv1.x); u.y = f2tf32(bv1.y); u.z = f2tf32(bv1.z); u.w = f2tf32(bv1.w);
            *(uint4*)&Bs[r1 * BKP + c41] = u;
        }
        __syncthreads();

        // prefetch next tile (overlaps with mma below)
        if (k0 + 16 < K) {
            av0 = *(const float4*)(Ap0 + k0 + 16);
            av1 = *(const float4*)(Ap1 + k0 + 16);
            bv0 = *(const float4*)(Bp0 + k0 + 16);
            bv1 = *(const float4*)(Bp1 + k0 + 16);
        }

        #pragma unroll
        for (int ks = 0; ks < 2; ks++) {
            int c = ks * 8 + lc;
            unsigned a[4][4], b[4][2];
            #pragma unroll
            for (int mf = 0; mf < 4; mf++) {
                int r = wm * 64 + mf * 16 + lr;
                a[mf][0] = As[r * BKP + c];
                a[mf][1] = As[(r + 8) * BKP + c];
                a[mf][2] = As[r * BKP + c + 4];
                a[mf][3] = As[(r + 8) * BKP + c + 4];
            }
            #pragma unroll
            for (int nf = 0; nf < 4; nf++) {
                int n = wn * 32 + nf * 8 + lr;
                b[nf][0] = Bs[n * BKP + c];
                b[nf][1] = Bs[n * BKP + c + 4];
            }
            #pragma unroll
            for (int mf = 0; mf < 4; mf++)
                #pragma unroll
                for (int nf = 0; nf < 4; nf++)
                    mma_tf32(acc[mf][nf], a[mf], b[nf]);
        }
        __syncthreads();
    }

    // epilogue: C fragment layout m16n8: (lane/4, (lane%4)*2) (+1), (+8 rows)
    #pragma unroll
    for (int mf = 0; mf < 4; mf++) {
        int row = mBase + wm * 64 + mf * 16 + lr;
        #pragma unroll
        for (int nf = 0; nf < 4; nf++) {
            int col = nBase + wn * 32 + nf * 8 + lc * 2;
            float2 v0 = {acc[mf][nf][0], acc[mf][nf][1]};
            float2 v1 = {acc[mf][nf][2], acc[mf][nf][3]};
            *(float2*)(C + (size_t)row * N + col)       = v0;
            *(float2*)(C + (size_t)(row + 8) * N + col) = v1;
        }
    }
}

// ---------------------------------------------------------------------------
// RMS-norm q and k rows in-place inside qkv: one warp per 128-elem row.
// ---------------------------------------------------------------------------
__global__ void __launch_bounds__(256) rmsnorm_qk(float* __restrict__ qkv)
{
    int gw = (blockIdx.x * blockDim.x + threadIdx.x) >> 5;
    int lane = threadIdx.x & 31;
    const int total = BB * SS * HH * 2;
    if (gw >= total) return;
    int which = gw & 1;          // 0=q, 1=k
    int t = gw >> 1;
    int h = t % HH;
    int bs = t / HH;
    float* p = qkv + (size_t)bs * F3D + which * DD + h * HD + lane * 4;
    float4 v = *(float4*)p;
    float ss = v.x*v.x + v.y*v.y + v.z*v.z + v.w*v.w;
    #pragma unroll
    for (int off = 16; off; off >>= 1) ss += __shfl_xor_sync(0xffffffffu, ss, off);
    float r = rsqrtf(ss * (1.f / HD) + 1e-6f);
    v.x *= r; v.y *= r; v.z *= r; v.w *= r;
    *(float4*)p = v;
}

// ---------------------------------------------------------------------------
// Causal flash attention, fp32 (unchanged this round).
// ---------------------------------------------------------------------------
__global__ void __launch_bounds__(256) flash_attn(
    const float* __restrict__ qkv, float* __restrict__ out)
{
    const int BM = 64, BN = 32;
    __shared__ float Ks[BN][HD];
    __shared__ float Vs[BN][HD];

    int tid = threadIdx.x;
    int row = tid >> 2, sub = tid & 3;
    int b = blockIdx.z, h = blockIdx.y;
    int qIdx = blockIdx.x * BM + row;

    const float* qptr = qkv + ((size_t)(b * SS + qIdx)) * F3D + h * HD + sub * 32;
    float qf[32];
    #pragma unroll
    for (int i = 0; i < 32; i += 4) {
        float4 t = *(const float4*)(qptr + i);
        qf[i] = t.x; qf[i+1] = t.y; qf[i+2] = t.z; qf[i+3] = t.w;
    }

    float o[32];
    #pragma unroll
    for (int i = 0; i < 32; i++) o[i] = 0.f;
    float m = -INFINITY, l = 0.f;
    const float scale = 0.08838834764831845f;  // 1/sqrt(128)

    int kEnd = (blockIdx.x + 1) * BM;
    for (int k0 = 0; k0 < kEnd; k0 += BN) {
        __syncthreads();
        for (int i = tid; i < BN * 32; i += 256) {
            int r = i >> 5;
            int c4 = (i & 31) * 4;
            const float* kp = qkv + ((size_t)(b * SS + k0 + r)) * F3D + DD + h * HD + c4;
            *(float4*)&Ks[r][c4] = *(const float4*)kp;
            *(float4*)&Vs[r][c4] = *(const float4*)(kp + DD);
        }
        __syncthreads();

        float s[BN];
        #pragma unroll
        for (int n = 0; n < BN; n++) {
            float acc = 0.f;
            #pragma unroll
            for (int d = 0; d < 32; d += 4) {
                float4 kv = *(const float4*)&Ks[n][sub * 32 + d];
                acc = fmaf(qf[d],   kv.x, acc);
                acc = fmaf(qf[d+1], kv.y, acc);
                acc = fmaf(qf[d+2], kv.z, acc);
                acc = fmaf(qf[d+3], kv.w, acc);
            }
            acc += __shfl_xor_sync(0xffffffffu, acc, 1);
            acc += __shfl_xor_sync(0xffffffffu, acc, 2);
            s[n] = (k0 + n > qIdx) ? -INFINITY : acc * scale;
        }
        float mt = m;
        #pragma unroll
        for (int n = 0; n < BN; n++) mt = fmaxf(mt, s[n]);
        float corr = __expf(m - mt);
        m = mt;
        float psum = 0.f;
        #pragma unroll
        for (int n = 0; n < BN; n++) { s[n] = __expf(s[n] - mt); psum += s[n]; }
        l = l * corr + psum;
        #pragma unroll
        for (int d = 0; d < 32; d++) o[d] *= corr;
        #pragma unroll
        for (int n = 0; n < BN; n++) {
            float pn = s[n];
            #pragma unroll
            for (int d = 0; d < 32; d += 4) {
                float4 vv = *(const float4*)&Vs[n][sub * 32 + d];
                o[d]   = fmaf(pn, vv.x, o[d]);
                o[d+1] = fmaf(pn, vv.y, o[d+1]);
                o[d+2] = fmaf(pn, vv.z, o[d+2]);
                o[d+3] = fmaf(pn, vv.w, o[d+3]);
            }
        }
    }

    float inv_l = 1.f / l;
    float ss = 0.f;
    #pragma unroll
    for (int d = 0; d < 32; d++) { o[d] *= inv_l; ss += o[d] * o[d]; }
    ss += __shfl_xor_sync(0xffffffffu, ss, 1);
    ss += __shfl_xor_sync(0xffffffffu, ss, 2);
    float r = rsqrtf(ss * (1.f / HD) + 1e-6f);
    float* op = out + ((size_t)(b * SS + qIdx)) * DD + h * HD + sub * 32;
    #pragma unroll
    for (int d = 0; d < 32; d += 4) {
        float4 t = {o[d] * r, o[d+1] * r, o[d+2] * r, o[d+3] * r};
        *(float4*)(op + d) = t;
    }
}

// ---------------------------------------------------------------------------
extern "C" void kernel_launch(void* const* d_in, const int* in_sizes, int n_in,
                              void* d_out, int out_size)
{
    const float* x = nullptr; const float* w_in = nullptr; const float* w_out = nullptr;
    for (int i = 0; i < n_in; i++) {
        if (in_sizes[i] == BB * SS * DD)      x     = (const float*)d_in[i];
        else if (in_sizes[i] == F3D * DD)     w_in  = (const float*)d_in[i];
        else if (in_sizes[i] == DD * DD)      w_out = (const float*)d_in[i];
    }

    float* win_n;  cudaGetSymbolAddress((void**)&win_n, g_win_n);
    float* wout_n; cudaGetSymbolAddress((void**)&wout_n, g_wout_n);
    float* qkv;    cudaGetSymbolAddress((void**)&qkv, g_qkv);
    float* a;      cudaGetSymbolAddress((void**)&a, g_a);

    // 1) normalize weights
    unit_norm_rows<<<F3D, 256>>>(w_in, win_n, DD);
    unit_norm_rows<<<DD, 256>>>(w_out, wout_n, DD);

    // 2) qkv = x @ w_in_n^T : [8192,6144]  (tf32 tensor cores)
    {
        dim3 grid(F3D / 128, MROWS / 128);
        gemm_tf32<<<grid, 256>>>(x, win_n, qkv, MROWS, F3D, DD);
    }

    // 3) rms_norm q,k rows (in place)
    {
        int totalWarps = BB * SS * HH * 2;
        int blocks = (totalWarps * 32 + 255) / 256;
        rmsnorm_qk<<<blocks, 256>>>(qkv);
    }

    // 4) flash attention + fused rms_norm -> g_a [8192,2048]
    {
        dim3 grid(SS / 64, HH, BB);
        flash_attn<<<grid, 256>>>(qkv, a);
    }

    // 5) out = a @ w_out_n^T : [8192,2048]  (tf32 tensor cores)
    {
        dim3 grid(DD / 128, MROWS / 128);
        gemm_tf32<<<grid, 256>>>(a, wout_n, (float*)d_out, MROWS, DD, DD);
    }
}

// round 4
// speedup vs baseline: 6.3794x; 4.8669x over previous
#include <cuda_runtime.h>
#include <math.h>
#include <cstdint>

// Problem constants
#define BB 4
#define SS 2048
#define DD 2048
#define HH 16
#define HD 128
#define F3D (3*DD)          // 6144
#define MROWS (BB*SS)       // 8192

// Scratch (device globals; no allocation allowed)
__device__ float g_win_n[F3D * DD];          // 6144x2048 normalized w_in
__device__ float g_wout_n[DD * DD];          // 2048x2048 normalized w_out
__device__ float g_qkv[(size_t)MROWS * F3D]; // 8192x6144
__device__ float g_a[(size_t)MROWS * DD];    // 8192x2048 (rms-normed attn out)

// ---------------------------------------------------------------------------
__device__ __forceinline__ unsigned f2tf32(float x) {
    unsigned u; asm("cvt.rna.tf32.f32 %0, %1;" : "=r"(u) : "f"(x)); return u;
}

__device__ __forceinline__ void mma_tf32(float* c, const unsigned* a, const unsigned* b) {
    asm volatile(
        "mma.sync.aligned.m16n8k8.row.col.f32.tf32.tf32.f32 "
        "{%0,%1,%2,%3}, {%4,%5,%6,%7}, {%8,%9}, {%0,%1,%2,%3};"
        : "+f"(c[0]), "+f"(c[1]), "+f"(c[2]), "+f"(c[3])
        : "r"(a[0]), "r"(a[1]), "r"(a[2]), "r"(a[3]), "r"(b[0]), "r"(b[1]));
}

// ---------------------------------------------------------------------------
// Row unit-normalize: out[r,:] = w[r,:] * rsqrt(sum(w[r,:]^2) + 1e-6)
// ---------------------------------------------------------------------------
__global__ void __launch_bounds__(256) unit_norm_rows(
    const float* __restrict__ w, float* __restrict__ o, int cols)
{
    int row = blockIdx.x, tid = threadIdx.x;
    const float* src = w + (size_t)row * cols;
    float* dst = o + (size_t)row * cols;
    float ss = 0.f;
    for (int i = tid * 4; i < cols; i += 1024) {
        float4 v = *(const float4*)(src + i);
        ss += v.x*v.x + v.y*v.y + v.z*v.z + v.w*v.w;
    }
    #pragma unroll
    for (int off = 16; off; off >>= 1) ss += __shfl_xor_sync(0xffffffffu, ss, off);
    __shared__ float red[8];
    if ((tid & 31) == 0) red[tid >> 5] = ss;
    __syncthreads();
    float total = 0.f;
    #pragma unroll
    for (int i = 0; i < 8; i++) total += red[i];
    float r = rsqrtf(total + 1e-6f);
    for (int i = tid * 4; i < cols; i += 1024) {
        float4 v = *(const float4*)(src + i);
        v.x *= r; v.y *= r; v.z *= r; v.w *= r;
        *(float4*)(dst + i) = v;
    }
}

// ---------------------------------------------------------------------------
// TF32 tensor-core GEMM (unchanged from round 2): C[m,n] = sum_k A[m,k]*B[n,k]
// ---------------------------------------------------------------------------
#define BKP 20
__global__ void __launch_bounds__(256, 2) gemm_tf32(
    const float* __restrict__ A, const float* __restrict__ B,
    float* __restrict__ C, int M, int N, int K)
{
    __shared__ unsigned As[128 * BKP];
    __shared__ unsigned Bs[128 * BKP];

    int tid = threadIdx.x, lane = tid & 31, warp = tid >> 5;
    int wm = warp >> 2, wn = warp & 3;
    int mBase = blockIdx.y * 128, nBase = blockIdx.x * 128;

    int r0 = tid >> 2,        c40 = (tid & 3) * 4;
    int r1 = (tid + 256) >> 2, c41 = c40;
    const float* Ap0 = A + (size_t)(mBase + r0) * K + c40;
    const float* Ap1 = A + (size_t)(mBase + r1) * K + c41;
    const float* Bp0 = B + (size_t)(nBase + r0) * K + c40;
    const float* Bp1 = B + (size_t)(nBase + r1) * K + c41;

    float acc[4][4][4];
    #pragma unroll
    for (int i = 0; i < 4; i++)
        #pragma unroll
        for (int j = 0; j < 4; j++)
            #pragma unroll
            for (int l = 0; l < 4; l++) acc[i][j][l] = 0.f;

    float4 av0 = *(const float4*)Ap0;
    float4 av1 = *(const float4*)Ap1;
    float4 bv0 = *(const float4*)Bp0;
    float4 bv1 = *(const float4*)Bp1;

    int lr = lane >> 2;
    int lc = lane & 3;

    for (int k0 = 0; k0 < K; k0 += 16) {
        {
            uint4 u;
            u.x = f2tf32(av0.x); u.y = f2tf32(av0.y); u.z = f2tf32(av0.z); u.w = f2tf32(av0.w);
            *(uint4*)&As[r0 * BKP + c40] = u;
            u.x = f2tf32(av1.x); u.y = f2tf32(av1.y); u.z = f2tf32(av1.z); u.w = f2tf32(av1.w);
            *(uint4*)&As[r1 * BKP + c41] = u;
            u.x = f2tf32(bv0.x); u.y = f2tf32(bv0.y); u.z = f2tf32(bv0.z); u.w = f2tf32(bv0.w);
            *(uint4*)&Bs[r0 * BKP + c40] = u;
            u.x = f2tf32(bv1.x); u.y = f2tf32(bv1.y); u.z = f2tf32(bv1.z); u.w = f2tf32(bv1.w);
            *(uint4*)&Bs[r1 * BKP + c41] = u;
        }
        __syncthreads();

        if (k0 + 16 < K) {
            av0 = *(const float4*)(Ap0 + k0 + 16);
            av1 = *(const float4*)(Ap1 + k0 + 16);
            bv0 = *(const float4*)(Bp0 + k0 + 16);
            bv1 = *(const float4*)(Bp1 + k0 + 16);
        }

        #pragma unroll
        for (int ks = 0; ks < 2; ks++) {
            int c = ks * 8 + lc;
            unsigned a[4][4], b[4][2];
            #pragma unroll
            for (int mf = 0; mf < 4; mf++) {
                int r = wm * 64 + mf * 16 + lr;
                a[mf][0] = As[r * BKP + c];
                a[mf][1] = As[(r + 8) * BKP + c];
                a[mf][2] = As[r * BKP + c + 4];
                a[mf][3] = As[(r + 8) * BKP + c + 4];
            }
            #pragma unroll
            for (int nf = 0; nf < 4; nf++) {
                int n = wn * 32 + nf * 8 + lr;
                b[nf][0] = Bs[n * BKP + c];
                b[nf][1] = Bs[n * BKP + c + 4];
            }
            #pragma unroll
            for (int mf = 0; mf < 4; mf++)
                #pragma unroll
                for (int nf = 0; nf < 4; nf++)
                    mma_tf32(acc[mf][nf], a[mf], b[nf]);
        }
        __syncthreads();
    }

    #pragma unroll
    for (int mf = 0; mf < 4; mf++) {
        int row = mBase + wm * 64 + mf * 16 + lr;
        #pragma unroll
        for (int nf = 0; nf < 4; nf++) {
            int col = nBase + wn * 32 + nf * 8 + lc * 2;
            float2 v0 = {acc[mf][nf][0], acc[mf][nf][1]};
            float2 v1 = {acc[mf][nf][2], acc[mf][nf][3]};
            *(float2*)(C + (size_t)row * N + col)       = v0;
            *(float2*)(C + (size_t)(row + 8) * N + col) = v1;
        }
    }
}

// ---------------------------------------------------------------------------
// RMS-norm q and k rows in-place inside qkv
// ---------------------------------------------------------------------------
__global__ void __launch_bounds__(256) rmsnorm_qk(float* __restrict__ qkv)
{
    int gw = (blockIdx.x * blockDim.x + threadIdx.x) >> 5;
    int lane = threadIdx.x & 31;
    const int total = BB * SS * HH * 2;
    if (gw >= total) return;
    int which = gw & 1;
    int t = gw >> 1;
    int h = t % HH;
    int bs = t / HH;
    float* p = qkv + (size_t)bs * F3D + which * DD + h * HD + lane * 4;
    float4 v = *(float4*)p;
    float ss = v.x*v.x + v.y*v.y + v.z*v.z + v.w*v.w;
    #pragma unroll
    for (int off = 16; off; off >>= 1) ss += __shfl_xor_sync(0xffffffffu, ss, off);
    float r = rsqrtf(ss * (1.f / HD) + 1e-6f);
    v.x *= r; v.y *= r; v.z *= r; v.w *= r;
    *(float4*)p = v;
}

// ---------------------------------------------------------------------------
// Tensor-core causal flash attention.
// BM=128 q rows/block, BN=64 keys/iter, 256 thr / 8 warps, warp owns 16 rows.
// QK^T: 3xTF32 (hi/lo split) for near-fp32 logits. PV: plain tf32.
// Fused epilogue: /l then rms_norm, write to out.
// smem: Qs fp32[128][132] | Ks fp32[64][132] | Vt tf32[128][68] (V^T) |
//       Ps tf32[128][68]
// ---------------------------------------------------------------------------
#define QS_ST 132
#define PS_ST 68
#define ATT_SMEM (128*132*4 + 64*132*4 + 128*68*4 + 128*68*4)

__global__ void __launch_bounds__(256) flash_attn_tc(
    const float* __restrict__ qkv, float* __restrict__ out)
{
    extern __shared__ __align__(16) char smem[];
    float*    Qs = (float*)smem;                          // [128][132]
    float*    Ks = (float*)(smem + 128*132*4);            // [64][132]
    unsigned* Vt = (unsigned*)(smem + 128*132*4 + 64*132*4); // [128][68] (d-major)
    unsigned* Ps = (unsigned*)(smem + 128*132*4 + 64*132*4 + 128*68*4); // [128][68]

    int tid = threadIdx.x, lane = tid & 31, wid = tid >> 5;
    int lr = lane >> 2, lc = lane & 3;
    int b = blockIdx.z, h = blockIdx.y, qb = blockIdx.x;
    int wrow = wid * 16;

    const float scale = 0.08838834764831845f;  // 1/sqrt(128)

    // ---- stage Q tile: rows qb*128.., 128 dims, fp32 ----
    {
        const float* qbase = qkv + ((size_t)(b * SS + qb * 128)) * F3D + h * HD;
        #pragma unroll
        for (int j = 0; j < 16; j++) {
            int lin = j * 256 + tid;            // 4096 float4 chunks
            int row = lin >> 5, q = (lin & 31) * 4;
            *(float4*)&Qs[row * QS_ST + q] = *(const float4*)(qbase + (size_t)row * F3D + q);
        }
    }

    // ---- accumulators ----
    float o[16][4];
    #pragma unroll
    for (int i = 0; i < 16; i++)
        #pragma unroll
        for (int j = 0; j < 4; j++) o[i][j] = 0.f;
    float m0 = -INFINITY, m1 = -INFINITY, l0 = 0.f, l1 = 0.f;

    int gr0 = qb * 128 + wrow + lr;   // global q row (and +8)
    int kEnd = (qb + 1) * 128;

    for (int k0 = 0; k0 < kEnd; k0 += 64) {
        __syncthreads();
        // stage K (fp32, natural) and V (tf32, transposed)
        {
            const float* kbase = qkv + ((size_t)(b * SS + k0)) * F3D + DD + h * HD;
            #pragma unroll
            for (int j = 0; j < 8; j++) {
                int lin = j * 256 + tid;        // 2048 chunks for K
                int row = lin >> 5, q = (lin & 31) * 4;
                *(float4*)&Ks[row * QS_ST + q] = *(const float4*)(kbase + (size_t)row * F3D + q);
            }
            const float* vbase = qkv + ((size_t)(b * SS + k0)) * F3D + 2 * DD + h * HD;
            #pragma unroll
            for (int j = 0; j < 8; j++) {
                int lin = j * 256 + tid;        // key = lin%64, chunk = lin/64
                int key = lin & 63, ch = lin >> 6;
                float4 v = *(const float4*)(vbase + (size_t)key * F3D + ch * 4);
                Vt[(ch * 4 + 0) * PS_ST + key] = f2tf32(v.x);
                Vt[(ch * 4 + 1) * PS_ST + key] = f2tf32(v.y);
                Vt[(ch * 4 + 2) * PS_ST + key] = f2tf32(v.z);
                Vt[(ch * 4 + 3) * PS_ST + key] = f2tf32(v.w);
            }
        }
        __syncthreads();

        // ---- S = Q K^T (3xTF32) ----
        float s[8][4];
        #pragma unroll
        for (int nf = 0; nf < 8; nf++)
            #pragma unroll
            for (int j = 0; j < 4; j++) s[nf][j] = 0.f;

        #pragma unroll
        for (int ks = 0; ks < 16; ks++) {
            int c = ks * 8 + lc;
            float af[4];
            af[0] = Qs[(wrow + lr) * QS_ST + c];
            af[1] = Qs[(wrow + lr + 8) * QS_ST + c];
            af[2] = Qs[(wrow + lr) * QS_ST + c + 4];
            af[3] = Qs[(wrow + lr + 8) * QS_ST + c + 4];
            unsigned ah[4], al[4];
            #pragma unroll
            for (int i = 0; i < 4; i++) {
                ah[i] = f2tf32(af[i]);
                al[i] = f2tf32(af[i] - __uint_as_float(ah[i]));
            }
            #pragma unroll
            for (int nf = 0; nf < 8; nf++) {
                float bf0 = Ks[(nf * 8 + lr) * QS_ST + c];
                float bf1 = Ks[(nf * 8 + lr) * QS_ST + c + 4];
                unsigned bh[2], bl[2];
                bh[0] = f2tf32(bf0); bl[0] = f2tf32(bf0 - __uint_as_float(bh[0]));
                bh[1] = f2tf32(bf1); bl[1] = f2tf32(bf1 - __uint_as_float(bh[1]));
                mma_tf32(s[nf], ah, bh);
                mma_tf32(s[nf], ah, bl);
                mma_tf32(s[nf], al, bh);
            }
        }

        // ---- scale + causal mask ----
        #pragma unroll
        for (int nf = 0; nf < 8; nf++) {
            int c0 = k0 + nf * 8 + lc * 2;
            s[nf][0] = (c0     > gr0)     ? -INFINITY : s[nf][0] * scale;
            s[nf][1] = (c0 + 1 > gr0)     ? -INFINITY : s[nf][1] * scale;
            s[nf][2] = (c0     > gr0 + 8) ? -INFINITY : s[nf][2] * scale;
            s[nf][3] = (c0 + 1 > gr0 + 8) ? -INFINITY : s[nf][3] * scale;
        }

        // ---- online softmax ----
        float mn0 = m0, mn1 = m1;
        #pragma unroll
        for (int nf = 0; nf < 8; nf++) {
            mn0 = fmaxf(mn0, fmaxf(s[nf][0], s[nf][1]));
            mn1 = fmaxf(mn1, fmaxf(s[nf][2], s[nf][3]));
        }
        mn0 = fmaxf(mn0, __shfl_xor_sync(0xffffffffu, mn0, 1));
        mn0 = fmaxf(mn0, __shfl_xor_sync(0xffffffffu, mn0, 2));
        mn1 = fmaxf(mn1, __shfl_xor_sync(0xffffffffu, mn1, 1));
        mn1 = fmaxf(mn1, __shfl_xor_sync(0xffffffffu, mn1, 2));

        float corr0 = __expf(m0 - mn0), corr1 = __expf(m1 - mn1);
        m0 = mn0; m1 = mn1;

        float ps0 = 0.f, ps1 = 0.f;
        #pragma unroll
        for (int nf = 0; nf < 8; nf++) {
            float p0 = __expf(s[nf][0] - mn0);
            float p1 = __expf(s[nf][1] - mn0);
            float p2 = __expf(s[nf][2] - mn1);
            float p3 = __expf(s[nf][3] - mn1);
            ps0 += p0 + p1; ps1 += p2 + p3;
            int col = nf * 8 + lc * 2;
            Ps[(wrow + lr) * PS_ST + col]       = f2tf32(p0);
            Ps[(wrow + lr) * PS_ST + col + 1]   = f2tf32(p1);
            Ps[(wrow + lr + 8) * PS_ST + col]     = f2tf32(p2);
            Ps[(wrow + lr + 8) * PS_ST + col + 1] = f2tf32(p3);
        }
        ps0 += __shfl_xor_sync(0xffffffffu, ps0, 1);
        ps0 += __shfl_xor_sync(0xffffffffu, ps0, 2);
        ps1 += __shfl_xor_sync(0xffffffffu, ps1, 1);
        ps1 += __shfl_xor_sync(0xffffffffu, ps1, 2);
        l0 = l0 * corr0 + ps0;
        l1 = l1 * corr1 + ps1;

        #pragma unroll
        for (int nf = 0; nf < 16; nf++) {
            o[nf][0] *= corr0; o[nf][1] *= corr0;
            o[nf][2] *= corr1; o[nf][3] *= corr1;
        }
        __syncwarp();

        // ---- O += P V  (tf32) ----
        #pragma unroll
        for (int ks = 0; ks < 8; ks++) {
            int kk = ks * 8 + lc;
            unsigned a[4];
            a[0] = Ps[(wrow + lr) * PS_ST + kk];
            a[1] = Ps[(wrow + lr + 8) * PS_ST + kk];
            a[2] = Ps[(wrow + lr) * PS_ST + kk + 4];
            a[3] = Ps[(wrow + lr + 8) * PS_ST + kk + 4];
            #pragma unroll
            for (int nf = 0; nf < 16; nf++) {
                unsigned bv[2];
                bv[0] = Vt[(nf * 8 + lr) * PS_ST + kk];
                bv[1] = Vt[(nf * 8 + lr) * PS_ST + kk + 4];
                mma_tf32(o[nf], a, bv);
            }
        }
        __syncwarp();
    }

    // ---- epilogue: /l, rms_norm over 128 dims, write ----
    float il0 = 1.f / l0, il1 = 1.f / l1;
    float ss0 = 0.f, ss1 = 0.f;
    #pragma unroll
    for (int nf = 0; nf < 16; nf++) {
        o[nf][0] *= il0; o[nf][1] *= il0;
        o[nf][2] *= il1; o[nf][3] *= il1;
        ss0 += o[nf][0]*o[nf][0] + o[nf][1]*o[nf][1];
        ss1 += o[nf][2]*o[nf][2] + o[nf][3]*o[nf][3];
    }
    ss0 += __shfl_xor_sync(0xffffffffu, ss0, 1);
    ss0 += __shfl_xor_sync(0xffffffffu, ss0, 2);
    ss1 += __shfl_xor_sync(0xffffffffu, ss1, 1);
    ss1 += __shfl_xor_sync(0xffffffffu, ss1, 2);
    float rn0 = rsqrtf(ss0 * (1.f / HD) + 1e-6f);
    float rn1 = rsqrtf(ss1 * (1.f / HD) + 1e-6f);

    float* o0 = out + ((size_t)(b * SS + gr0)) * DD + h * HD;
    float* o1 = out + ((size_t)(b * SS + gr0 + 8)) * DD + h * HD;
    #pragma unroll
    for (int nf = 0; nf < 16; nf++) {
        int col = nf * 8 + lc * 2;
        float2 v0 = {o[nf][0] * rn0, o[nf][1] * rn0};
        float2 v1 = {o[nf][2] * rn1, o[nf][3] * rn1};
        *(float2*)(o0 + col) = v0;
        *(float2*)(o1 + col) = v1;
    }
}

// ---------------------------------------------------------------------------
extern "C" void kernel_launch(void* const* d_in, const int* in_sizes, int n_in,
                              void* d_out, int out_size)
{
    const float* x = nullptr; const float* w_in = nullptr; const float* w_out = nullptr;
    for (int i = 0; i < n_in; i++) {
        if (in_sizes[i] == BB * SS * DD)      x     = (const float*)d_in[i];
        else if (in_sizes[i] == F3D * DD)     w_in  = (const float*)d_in[i];
        else if (in_sizes[i] == DD * DD)      w_out = (const float*)d_in[i];
    }

    float* win_n;  cudaGetSymbolAddress((void**)&win_n, g_win_n);
    float* wout_n; cudaGetSymbolAddress((void**)&wout_n, g_wout_n);
    float* qkv;    cudaGetSymbolAddress((void**)&qkv, g_qkv);
    float* a;      cudaGetSymbolAddress((void**)&a, g_a);

    cudaFuncSetAttribute(flash_attn_tc, cudaFuncAttributeMaxDynamicSharedMemorySize, ATT_SMEM);

    // 1) normalize weights
    unit_norm_rows<<<F3D, 256>>>(w_in, win_n, DD);
    unit_norm_rows<<<DD, 256>>>(w_out, wout_n, DD);

    // 2) qkv = x @ w_in_n^T : [8192,6144]
    {
        dim3 grid(F3D / 128, MROWS / 128);
        gemm_tf32<<<grid, 256>>>(x, win_n, qkv, MROWS, F3D, DD);
    }

    // 3) rms_norm q,k rows (in place)
    {
        int totalWarps = BB * SS * HH * 2;
        int blocks = (totalWarps * 32 + 255) / 256;
        rmsnorm_qk<<<blocks, 256>>>(qkv);
    }

    // 4) tensor-core flash attention + fused rms_norm -> g_a
    {
        dim3 grid(SS / 128, HH, BB);
        flash_attn_tc<<<grid, 256, ATT_SMEM>>>(qkv, a);
    }

    // 5) out = a @ w_out_n^T : [8192,2048]
    {
        dim3 grid(DD / 128, MROWS / 128);
        gemm_tf32<<<grid, 256>>>(a, wout_n, (float*)d_out, MROWS, DD, DD);
    }
}

// round 6
// speedup vs baseline: 6.8011x; 1.0661x over previous
#include <cuda_runtime.h>
#include <math.h>
#include <cstdint>

// Problem constants
#define BB 4
#define SS 2048
#define DD 2048
#define HH 16
#define HD 128
#define F3D (3*DD)          // 6144
#define MROWS (BB*SS)       // 8192

// Scratch (device globals; no allocation allowed)
__device__ float g_win_n[F3D * DD];          // 6144x2048 normalized w_in
__device__ float g_wout_n[DD * DD];          // 2048x2048 normalized w_out
__device__ float g_qkv[(size_t)MROWS * F3D]; // 8192x6144
__device__ float g_a[(size_t)MROWS * DD];    // 8192x2048 (rms-normed attn out)

// single dynamic smem symbol shared by all kernels
extern __shared__ __align__(16) char dyn_smem[];

// ---------------------------------------------------------------------------
__device__ __forceinline__ unsigned f2tf32(float x) {
    unsigned u; asm("cvt.rna.tf32.f32 %0, %1;" : "=r"(u) : "f"(x)); return u;
}
__device__ __forceinline__ uint32_t smem_to_u32(const void* p) {
    uint32_t a;
    asm("{ .reg .u64 t; cvta.to.shared.u64 t, %1; cvt.u32.u64 %0, t; }" : "=r"(a) : "l"(p));
    return a;
}
__device__ __forceinline__ void cp_async16(uint32_t saddr, const void* gptr) {
    asm volatile("cp.async.cg.shared.global [%0], [%1], 16;" :: "r"(saddr), "l"(gptr));
}
#define CP_COMMIT() asm volatile("cp.async.commit_group;" ::: "memory")
#define CP_WAIT1()  asm volatile("cp.async.wait_group 1;" ::: "memory")

__device__ __forceinline__ void mma_tf32(float* c, const unsigned* a, const unsigned* b) {
    asm volatile(
        "mma.sync.aligned.m16n8k8.row.col.f32.tf32.tf32.f32 "
        "{%0,%1,%2,%3}, {%4,%5,%6,%7}, {%8,%9}, {%0,%1,%2,%3};"
        : "+f"(c[0]), "+f"(c[1]), "+f"(c[2]), "+f"(c[3])
        : "r"(a[0]), "r"(a[1]), "r"(a[2]), "r"(a[3]), "r"(b[0]), "r"(b[1]));
}

// ---------------------------------------------------------------------------
// Row unit-normalize: out[r,:] = w[r,:] * rsqrt(sum(w[r,:]^2) + 1e-6)
// ---------------------------------------------------------------------------
__global__ void __launch_bounds__(256) unit_norm_rows(
    const float* __restrict__ w, float* __restrict__ o, int cols)
{
    int row = blockIdx.x, tid = threadIdx.x;
    const float* src = w + (size_t)row * cols;
    float* dst = o + (size_t)row * cols;
    float ss = 0.f;
    for (int i = tid * 4; i < cols; i += 1024) {
        float4 v = *(const float4*)(src + i);
        ss += v.x*v.x + v.y*v.y + v.z*v.z + v.w*v.w;
    }
    #pragma unroll
    for (int off = 16; off; off >>= 1) ss += __shfl_xor_sync(0xffffffffu, ss, off);
    __shared__ float red[8];
    if ((tid & 31) == 0) red[tid >> 5] = ss;
    __syncthreads();
    float total = 0.f;
    #pragma unroll
    for (int i = 0; i < 8; i++) total += red[i];
    float r = rsqrtf(total + 1e-6f);
    for (int i = tid * 4; i < cols; i += 1024) {
        float4 v = *(const float4*)(src + i);
        v.x *= r; v.y *= r; v.z *= r; v.w *= r;
        *(float4*)(dst + i) = v;
    }
}

// ---------------------------------------------------------------------------
// TF32 tensor-core GEMM with 3-stage cp.async pipeline.
// C[m,n] = sum_k A[m,k]*B[n,k]; A: MxK row-major, B: NxK row-major.
// BM=BN=128, BK=16, 256 thr, 8 warps, warp tile 64x32, mma m16n8k8.
// smem: raw fp32, stride 20 words (conflict-free); cvt->tf32 at frag load.
// Stage = [A 128x20][B 128x20] = 5120 words; 3 stages = 61440 B dynamic.
// ---------------------------------------------------------------------------
#define GBKP 20
#define GSTG 5120
#define GEMM_SMEM (3 * GSTG * 4)

__global__ void __launch_bounds__(256, 2) gemm_tf32(
    const float* __restrict__ A, const float* __restrict__ B,
    float* __restrict__ C, int M, int N, int K)
{
    float* smem = (float*)dyn_smem;

    int tid = threadIdx.x, lane = tid & 31, warp = tid >> 5;
    int wm = warp >> 2, wn = warp & 3;
    int mBase = blockIdx.y * 128, nBase = blockIdx.x * 128;
    int lr = lane >> 2, lc = lane & 3;

    // global-load mapping: rows r0 and r0+64, 4-col chunk c4
    int r0 = tid >> 2, c4 = (tid & 3) * 4;
    const float* Ap0 = A + (size_t)(mBase + r0) * K + c4;
    const float* Ap1 = A + (size_t)(mBase + r0 + 64) * K + c4;
    const float* Bp0 = B + (size_t)(nBase + r0) * K + c4;
    const float* Bp1 = B + (size_t)(nBase + r0 + 64) * K + c4;

    uint32_t sb = smem_to_u32(smem);
    uint32_t sA0 = sb + (r0 * GBKP + c4) * 4;
    uint32_t sA1 = sb + ((r0 + 64) * GBKP + c4) * 4;
    uint32_t sB0 = sA0 + 2560 * 4;
    uint32_t sB1 = sA1 + 2560 * 4;

    float acc[4][4][4];
    #pragma unroll
    for (int i = 0; i < 4; i++)
        #pragma unroll
        for (int j = 0; j < 4; j++)
            #pragma unroll
            for (int l = 0; l < 4; l++) acc[i][j][l] = 0.f;

    const int T = K / 16;

    // prime stages 0,1
    #pragma unroll
    for (int s = 0; s < 2; s++) {
        uint32_t so = s * (GSTG * 4);
        int k0 = s * 16;
        cp_async16(sA0 + so, Ap0 + k0);
        cp_async16(sA1 + so, Ap1 + k0);
        cp_async16(sB0 + so, Bp0 + k0);
        cp_async16(sB1 + so, Bp1 + k0);
        CP_COMMIT();
    }

    for (int t = 0; t < T; t++) {
        CP_WAIT1();          // stage t resident
        __syncthreads();     // all readers of stage (t+2)%3 done (iter t-1)

        // issue stage t+2 into buffer (t+2)%3
        if (t + 2 < T) {
            uint32_t so = ((t + 2) % 3) * (GSTG * 4);
            int k0 = (t + 2) * 16;
            cp_async16(sA0 + so, Ap0 + k0);
            cp_async16(sA1 + so, Ap1 + k0);
            cp_async16(sB0 + so, Bp0 + k0);
            cp_async16(sB1 + so, Bp1 + k0);
        }
        CP_COMMIT();

        // compute on stage t%3
        const float* As = smem + (t % 3) * GSTG;
        const float* Bs = As + 2560;
        #pragma unroll
        for (int ks = 0; ks < 2; ks++) {
            int c = ks * 8 + lc;
            unsigned a[4][4], b[4][2];
            #pragma unroll
            for (int mf = 0; mf < 4; mf++) {
                int r = wm * 64 + mf * 16 + lr;
                a[mf][0] = f2tf32(As[r * GBKP + c]);
                a[mf][1] = f2tf32(As[(r + 8) * GBKP + c]);
                a[mf][2] = f2tf32(As[r * GBKP + c + 4]);
                a[mf][3] = f2tf32(As[(r + 8) * GBKP + c + 4]);
            }
            #pragma unroll
            for (int nf = 0; nf < 4; nf++) {
                int n = wn * 32 + nf * 8 + lr;
                b[nf][0] = f2tf32(Bs[n * GBKP + c]);
                b[nf][1] = f2tf32(Bs[n * GBKP + c + 4]);
            }
            #pragma unroll
            for (int mf = 0; mf < 4; mf++)
                #pragma unroll
                for (int nf = 0; nf < 4; nf++)
                    mma_tf32(acc[mf][nf], a[mf], b[nf]);
        }
    }

    #pragma unroll
    for (int mf = 0; mf < 4; mf++) {
        int row = mBase + wm * 64 + mf * 16 + lr;
        #pragma unroll
        for (int nf = 0; nf < 4; nf++) {
            int col = nBase + wn * 32 + nf * 8 + lc * 2;
            float2 v0 = {acc[mf][nf][0], acc[mf][nf][1]};
            float2 v1 = {acc[mf][nf][2], acc[mf][nf][3]};
            *(float2*)(C + (size_t)row * N + col)       = v0;
            *(float2*)(C + (size_t)(row + 8) * N + col) = v1;
        }
    }
}

// ---------------------------------------------------------------------------
// RMS-norm q and k rows in-place inside qkv
// ---------------------------------------------------------------------------
__global__ void __launch_bounds__(256) rmsnorm_qk(float* __restrict__ qkv)
{
    int gw = (blockIdx.x * blockDim.x + threadIdx.x) >> 5;
    int lane = threadIdx.x & 31;
    const int total = BB * SS * HH * 2;
    if (gw >= total) return;
    int which = gw & 1;
    int t = gw >> 1;
    int h = t % HH;
    int bs = t / HH;
    float* p = qkv + (size_t)bs * F3D + which * DD + h * HD + lane * 4;
    float4 v = *(float4*)p;
    float ss = v.x*v.x + v.y*v.y + v.z*v.z + v.w*v.w;
    #pragma unroll
    for (int off = 16; off; off >>= 1) ss += __shfl_xor_sync(0xffffffffu, ss, off);
    float r = rsqrtf(ss * (1.f / HD) + 1e-6f);
    v.x *= r; v.y *= r; v.z *= r; v.w *= r;
    *(float4*)p = v;
}

// ---------------------------------------------------------------------------
// Tensor-core causal flash attention (same as round 4).
// ---------------------------------------------------------------------------
#define QS_ST 132
#define PS_ST 68
#define ATT_SMEM (128*132*4 + 64*132*4 + 128*68*4 + 128*68*4)

__global__ void __launch_bounds__(256) flash_attn_tc(
    const float* __restrict__ qkv, float* __restrict__ out)
{
    char* smem = dyn_smem;
    float*    Qs = (float*)smem;                          // [128][132]
    float*    Ks = (float*)(smem + 128*132*4);            // [64][132]
    unsigned* Vt = (unsigned*)(smem + 128*132*4 + 64*132*4); // [128][68] (d-major)
    unsigned* Ps = (unsigned*)(smem + 128*132*4 + 64*132*4 + 128*68*4); // [128][68]

    int tid = threadIdx.x, lane = tid & 31, wid = tid >> 5;
    int lr = lane >> 2, lc = lane & 3;
    int b = blockIdx.z, h = blockIdx.y, qb = blockIdx.x;
    int wrow = wid * 16;

    const float scale = 0.08838834764831845f;  // 1/sqrt(128)

    {
        const float* qbase = qkv + ((size_t)(b * SS + qb * 128)) * F3D + h * HD;
        #pragma unroll
        for (int j = 0; j < 16; j++) {
            int lin = j * 256 + tid;
            int row = lin >> 5, q = (lin & 31) * 4;
            *(float4*)&Qs[row * QS_ST + q] = *(const float4*)(qbase + (size_t)row * F3D + q);
        }
    }

    float o[16][4];
    #pragma unroll
    for (int i = 0; i < 16; i++)
        #pragma unroll
        for (int j = 0; j < 4; j++) o[i][j] = 0.f;
    float m0 = -INFINITY, m1 = -INFINITY, l0 = 0.f, l1 = 0.f;

    int gr0 = qb * 128 + wrow + lr;
    int kEnd = (qb + 1) * 128;

    for (int k0 = 0; k0 < kEnd; k0 += 64) {
        __syncthreads();
        {
            const float* kbase = qkv + ((size_t)(b * SS + k0)) * F3D + DD + h * HD;
            #pragma unroll
            for (int j = 0; j < 8; j++) {
                int lin = j * 256 + tid;
                int row = lin >> 5, q = (lin & 31) * 4;
                *(float4*)&Ks[row * QS_ST + q] = *(const float4*)(kbase + (size_t)row * F3D + q);
            }
            const float* vbase = qkv + ((size_t)(b * SS + k0)) * F3D + 2 * DD + h * HD;
            #pragma unroll
            for (int j = 0; j < 8; j++) {
                int lin = j * 256 + tid;
                int key = lin & 63, ch = lin >> 6;
                float4 v = *(const float4*)(vbase + (size_t)key * F3D + ch * 4);
                Vt[(ch * 4 + 0) * PS_ST + key] = f2tf32(v.x);
                Vt[(ch * 4 + 1) * PS_ST + key] = f2tf32(v.y);
                Vt[(ch * 4 + 2) * PS_ST + key] = f2tf32(v.z);
                Vt[(ch * 4 + 3) * PS_ST + key] = f2tf32(v.w);
            }
        }
        __syncthreads();

        float s[8][4];
        #pragma unroll
        for (int nf = 0; nf < 8; nf++)
            #pragma unroll
            for (int j = 0; j < 4; j++) s[nf][j] = 0.f;

        #pragma unroll
        for (int ks = 0; ks < 16; ks++) {
            int c = ks * 8 + lc;
            float af[4];
            af[0] = Qs[(wrow + lr) * QS_ST + c];
            af[1] = Qs[(wrow + lr + 8) * QS_ST + c];
            af[2] = Qs[(wrow + lr) * QS_ST + c + 4];
            af[3] = Qs[(wrow + lr + 8) * QS_ST + c + 4];
            unsigned ah[4], al[4];
            #pragma unroll
            for (int i = 0; i < 4; i++) {
                ah[i] = f2tf32(af[i]);
                al[i] = f2tf32(af[i] - __uint_as_float(ah[i]));
            }
            #pragma unroll
            for (int nf = 0; nf < 8; nf++) {
                float bf0 = Ks[(nf * 8 + lr) * QS_ST + c];
                float bf1 = Ks[(nf * 8 + lr) * QS_ST + c + 4];
                unsigned bh[2], bl[2];
                bh[0] = f2tf32(bf0); bl[0] = f2tf32(bf0 - __uint_as_float(bh[0]));
                bh[1] = f2tf32(bf1); bl[1] = f2tf32(bf1 - __uint_as_float(bh[1]));
                mma_tf32(s[nf], ah, bh);
                mma_tf32(s[nf], ah, bl);
                mma_tf32(s[nf], al, bh);
            }
        }

        #pragma unroll
        for (int nf = 0; nf < 8; nf++) {
            int c0 = k0 + nf * 8 + lc * 2;
            s[nf][0] = (c0     > gr0)     ? -INFINITY : s[nf][0] * scale;
            s[nf][1] = (c0 + 1 > gr0)     ? -INFINITY : s[nf][1] * scale;
            s[nf][2] = (c0     > gr0 + 8) ? -INFINITY : s[nf][2] * scale;
            s[nf][3] = (c0 + 1 > gr0 + 8) ? -INFINITY : s[nf][3] * scale;
        }

        float mn0 = m0, mn1 = m1;
        #pragma unroll
        for (int nf = 0; nf < 8; nf++) {
            mn0 = fmaxf(mn0, fmaxf(s[nf][0], s[nf][1]));
            mn1 = fmaxf(mn1, fmaxf(s[nf][2], s[nf][3]));
        }
        mn0 = fmaxf(mn0, __shfl_xor_sync(0xffffffffu, mn0, 1));
        mn0 = fmaxf(mn0, __shfl_xor_sync(0xffffffffu, mn0, 2));
        mn1 = fmaxf(mn1, __shfl_xor_sync(0xffffffffu, mn1, 1));
        mn1 = fmaxf(mn1, __shfl_xor_sync(0xffffffffu, mn1, 2));

        float corr0 = __expf(m0 - mn0), corr1 = __expf(m1 - mn1);
        m0 = mn0; m1 = mn1;

        float ps0 = 0.f, ps1 = 0.f;
        #pragma unroll
        for (int nf = 0; nf < 8; nf++) {
            float p0 = __expf(s[nf][0] - mn0);
            float p1 = __expf(s[nf][1] - mn0);
            float p2 = __expf(s[nf][2] - mn1);
            float p3 = __expf(s[nf][3] - mn1);
            ps0 += p0 + p1; ps1 += p2 + p3;
            int col = nf * 8 + lc * 2;
            Ps[(wrow + lr) * PS_ST + col]       = f2tf32(p0);
            Ps[(wrow + lr) * PS_ST + col + 1]   = f2tf32(p1);
            Ps[(wrow + lr + 8) * PS_ST + col]     = f2tf32(p2);
            Ps[(wrow + lr + 8) * PS_ST + col + 1] = f2tf32(p3);
        }
        ps0 += __shfl_xor_sync(0xffffffffu, ps0, 1);
        ps0 += __shfl_xor_sync(0xffffffffu, ps0, 2);
        ps1 += __shfl_xor_sync(0xffffffffu, ps1, 1);
        ps1 += __shfl_xor_sync(0xffffffffu, ps1, 2);
        l0 = l0 * corr0 + ps0;
        l1 = l1 * corr1 + ps1;

        #pragma unroll
        for (int nf = 0; nf < 16; nf++) {
            o[nf][0] *= corr0; o[nf][1] *= corr0;
            o[nf][2] *= corr1; o[nf][3] *= corr1;
        }
        __syncwarp();

        #pragma unroll
        for (int ks = 0; ks < 8; ks++) {
            int kk = ks * 8 + lc;
            unsigned a[4];
            a[0] = Ps[(wrow + lr) * PS_ST + kk];
            a[1] = Ps[(wrow + lr + 8) * PS_ST + kk];
            a[2] = Ps[(wrow + lr) * PS_ST + kk + 4];
            a[3] = Ps[(wrow + lr + 8) * PS_ST + kk + 4];
            #pragma unroll
            for (int nf = 0; nf < 16; nf++) {
                unsigned bv[2];
                bv[0] = Vt[(nf * 8 + lr) * PS_ST + kk];
                bv[1] = Vt[(nf * 8 + lr) * PS_ST + kk + 4];
                mma_tf32(o[nf], a, bv);
            }
        }
        __syncwarp();
    }

    float il0 = 1.f / l0, il1 = 1.f / l1;
    float ss0 = 0.f, ss1 = 0.f;
    #pragma unroll
    for (int nf = 0; nf < 16; nf++) {
        o[nf][0] *= il0; o[nf][1] *= il0;
        o[nf][2] *= il1; o[nf][3] *= il1;
        ss0 += o[nf][0]*o[nf][0] + o[nf][1]*o[nf][1];
        ss1 += o[nf][2]*o[nf][2] + o[nf][3]*o[nf][3];
    }
    ss0 += __shfl_xor_sync(0xffffffffu, ss0, 1);
    ss0 += __shfl_xor_sync(0xffffffffu, ss0, 2);
    ss1 += __shfl_xor_sync(0xffffffffu, ss1, 1);
    ss1 += __shfl_xor_sync(0xffffffffu, ss1, 2);
    float rn0 = rsqrtf(ss0 * (1.f / HD) + 1e-6f);
    float rn1 = rsqrtf(ss1 * (1.f / HD) + 1e-6f);

    float* o0 = out + ((size_t)(b * SS + gr0)) * DD + h * HD;
    float* o1 = out + ((size_t)(b * SS + gr0 + 8)) * DD + h * HD;
    #pragma unroll
    for (int nf = 0; nf < 16; nf++) {
        int col = nf * 8 + lc * 2;
        float2 v0 = {o[nf][0] * rn0, o[nf][1] * rn0};
        float2 v1 = {o[nf][2] * rn1, o[nf][3] * rn1};
        *(float2*)(o0 + col) = v0;
        *(float2*)(o1 + col) = v1;
    }
}

// ---------------------------------------------------------------------------
extern "C" void kernel_launch(void* const* d_in, const int* in_sizes, int n_in,
                              void* d_out, int out_size)
{
    const float* x = nullptr; const float* w_in = nullptr; const float* w_out = nullptr;
    for (int i = 0; i < n_in; i++) {
        if (in_sizes[i] == BB * SS * DD)      x     = (const float*)d_in[i];
        else if (in_sizes[i] == F3D * DD)     w_in  = (const float*)d_in[i];
        else if (in_sizes[i] == DD * DD)      w_out = (const float*)d_in[i];
    }

    float* win_n;  cudaGetSymbolAddress((void**)&win_n, g_win_n);
    float* wout_n; cudaGetSymbolAddress((void**)&wout_n, g_wout_n);
    float* qkv;    cudaGetSymbolAddress((void**)&qkv, g_qkv);
    float* a;      cudaGetSymbolAddress((void**)&a, g_a);

    cudaFuncSetAttribute(gemm_tf32, cudaFuncAttributeMaxDynamicSharedMemorySize, GEMM_SMEM);
    cudaFuncSetAttribute(flash_attn_tc, cudaFuncAttributeMaxDynamicSharedMemorySize, ATT_SMEM);

    // 1) normalize weights
    unit_norm_rows<<<F3D, 256>>>(w_in, win_n, DD);
    unit_norm_rows<<<DD, 256>>>(w_out, wout_n, DD);

    // 2) qkv = x @ w_in_n^T : [8192,6144]
    {
        dim3 grid(F3D / 128, MROWS / 128);
        gemm_tf32<<<grid, 256, GEMM_SMEM>>>(x, win_n, qkv, MROWS, F3D, DD);
    }

    // 3) rms_norm q,k rows (in place)
    {
        int totalWarps = BB * SS * HH * 2;
        int blocks = (totalWarps * 32 + 255) / 256;
        rmsnorm_qk<<<blocks, 256>>>(qkv);
    }

    // 4) tensor-core flash attention + fused rms_norm -> g_a
    {
        dim3 grid(SS / 128, HH, BB);
        flash_attn_tc<<<grid, 256, ATT_SMEM>>>(qkv, a);
    }

    // 5) out = a @ w_out_n^T : [8192,2048]
    {
        dim3 grid(DD / 128, MROWS / 128);
        gemm_tf32<<<grid, 256, GEMM_SMEM>>>(a, wout_n, (float*)d_out, MROWS, DD, DD);
    }
}

// round 7
// speedup vs baseline: 7.1750x; 1.0550x over previous
#include <cuda_runtime.h>
#include <math.h>
#include <cstdint>

// Problem constants
#define BB 4
#define SS 2048
#define DD 2048
#define HH 16
#define HD 128
#define F3D (3*DD)          // 6144
#define MROWS (BB*SS)       // 8192

// Scratch (device globals; no allocation allowed)
__device__ float g_win_n[F3D * DD];          // 6144x2048 normalized w_in
__device__ float g_wout_n[DD * DD];          // 2048x2048 normalized w_out
__device__ float g_qkv[(size_t)MROWS * F3D]; // 8192x6144
__device__ float g_a[(size_t)MROWS * DD];    // 8192x2048 (rms-normed attn out)

// single dynamic smem symbol shared by all kernels
extern __shared__ __align__(16) char dyn_smem[];

// ---------------------------------------------------------------------------
__device__ __forceinline__ unsigned f2tf32(float x) {
    unsigned u; asm("cvt.rna.tf32.f32 %0, %1;" : "=r"(u) : "f"(x)); return u;
}
__device__ __forceinline__ uint32_t smem_to_u32(const void* p) {
    uint32_t a;
    asm("{ .reg .u64 t; cvta.to.shared.u64 t, %1; cvt.u32.u64 %0, t; }" : "=r"(a) : "l"(p));
    return a;
}
__device__ __forceinline__ void cp_async16(uint32_t saddr, const void* gptr) {
    asm volatile("cp.async.cg.shared.global [%0], [%1], 16;" :: "r"(saddr), "l"(gptr));
}
#define CP_COMMIT() asm volatile("cp.async.commit_group;" ::: "memory")
#define CP_WAIT1()  asm volatile("cp.async.wait_group 1;" ::: "memory")

__device__ __forceinline__ void mma_tf32(float* c, const unsigned* a, const unsigned* b) {
    asm volatile(
        "mma.sync.aligned.m16n8k8.row.col.f32.tf32.tf32.f32 "
        "{%0,%1,%2,%3}, {%4,%5,%6,%7}, {%8,%9}, {%0,%1,%2,%3};"
        : "+f"(c[0]), "+f"(c[1]), "+f"(c[2]), "+f"(c[3])
        : "r"(a[0]), "r"(a[1]), "r"(a[2]), "r"(a[3]), "r"(b[0]), "r"(b[1]));
}

// ---------------------------------------------------------------------------
// Row unit-normalize: out[r,:] = w[r,:] * rsqrt(sum(w[r,:]^2) + 1e-6)
// ---------------------------------------------------------------------------
__global__ void __launch_bounds__(256) unit_norm_rows(
    const float* __restrict__ w, float* __restrict__ o, int cols)
{
    int row = blockIdx.x, tid = threadIdx.x;
    const float* src = w + (size_t)row * cols;
    float* dst = o + (size_t)row * cols;
    float ss = 0.f;
    for (int i = tid * 4; i < cols; i += 1024) {
        float4 v = *(const float4*)(src + i);
        ss += v.x*v.x + v.y*v.y + v.z*v.z + v.w*v.w;
    }
    #pragma unroll
    for (int off = 16; off; off >>= 1) ss += __shfl_xor_sync(0xffffffffu, ss, off);
    __shared__ float red[8];
    if ((tid & 31) == 0) red[tid >> 5] = ss;
    __syncthreads();
    float total = 0.f;
    #pragma unroll
    for (int i = 0; i < 8; i++) total += red[i];
    float r = rsqrtf(total + 1e-6f);
    for (int i = tid * 4; i < cols; i += 1024) {
        float4 v = *(const float4*)(src + i);
        v.x *= r; v.y *= r; v.z *= r; v.w *= r;
        *(float4*)(dst + i) = v;
    }
}

// ---------------------------------------------------------------------------
// TF32 tensor-core GEMM with 3-stage cp.async pipeline (unchanged).
// ---------------------------------------------------------------------------
#define GBKP 20
#define GSTG 5120
#define GEMM_SMEM (3 * GSTG * 4)

__global__ void __launch_bounds__(256, 2) gemm_tf32(
    const float* __restrict__ A, const float* __restrict__ B,
    float* __restrict__ C, int M, int N, int K)
{
    float* smem = (float*)dyn_smem;

    int tid = threadIdx.x, lane = tid & 31, warp = tid >> 5;
    int wm = warp >> 2, wn = warp & 3;
    int mBase = blockIdx.y * 128, nBase = blockIdx.x * 128;
    int lr = lane >> 2, lc = lane & 3;

    int r0 = tid >> 2, c4 = (tid & 3) * 4;
    const float* Ap0 = A + (size_t)(mBase + r0) * K + c4;
    const float* Ap1 = A + (size_t)(mBase + r0 + 64) * K + c4;
    const float* Bp0 = B + (size_t)(nBase + r0) * K + c4;
    const float* Bp1 = B + (size_t)(nBase + r0 + 64) * K + c4;

    uint32_t sb = smem_to_u32(smem);
    uint32_t sA0 = sb + (r0 * GBKP + c4) * 4;
    uint32_t sA1 = sb + ((r0 + 64) * GBKP + c4) * 4;
    uint32_t sB0 = sA0 + 2560 * 4;
    uint32_t sB1 = sA1 + 2560 * 4;

    float acc[4][4][4];
    #pragma unroll
    for (int i = 0; i < 4; i++)
        #pragma unroll
        for (int j = 0; j < 4; j++)
            #pragma unroll
            for (int l = 0; l < 4; l++) acc[i][j][l] = 0.f;

    const int T = K / 16;

    #pragma unroll
    for (int s = 0; s < 2; s++) {
        uint32_t so = s * (GSTG * 4);
        int k0 = s * 16;
        cp_async16(sA0 + so, Ap0 + k0);
        cp_async16(sA1 + so, Ap1 + k0);
        cp_async16(sB0 + so, Bp0 + k0);
        cp_async16(sB1 + so, Bp1 + k0);
        CP_COMMIT();
    }

    for (int t = 0; t < T; t++) {
        CP_WAIT1();
        __syncthreads();

        if (t + 2 < T) {
            uint32_t so = ((t + 2) % 3) * (GSTG * 4);
            int k0 = (t + 2) * 16;
            cp_async16(sA0 + so, Ap0 + k0);
            cp_async16(sA1 + so, Ap1 + k0);
            cp_async16(sB0 + so, Bp0 + k0);
            cp_async16(sB1 + so, Bp1 + k0);
        }
        CP_COMMIT();

        const float* As = smem + (t % 3) * GSTG;
        const float* Bs = As + 2560;
        #pragma unroll
        for (int ks = 0; ks < 2; ks++) {
            int c = ks * 8 + lc;
            unsigned a[4][4], b[4][2];
            #pragma unroll
            for (int mf = 0; mf < 4; mf++) {
                int r = wm * 64 + mf * 16 + lr;
                a[mf][0] = f2tf32(As[r * GBKP + c]);
                a[mf][1] = f2tf32(As[(r + 8) * GBKP + c]);
                a[mf][2] = f2tf32(As[r * GBKP + c + 4]);
                a[mf][3] = f2tf32(As[(r + 8) * GBKP + c + 4]);
            }
            #pragma unroll
            for (int nf = 0; nf < 4; nf++) {
                int n = wn * 32 + nf * 8 + lr;
                b[nf][0] = f2tf32(Bs[n * GBKP + c]);
                b[nf][1] = f2tf32(Bs[n * GBKP + c + 4]);
            }
            #pragma unroll
            for (int mf = 0; mf < 4; mf++)
                #pragma unroll
                for (int nf = 0; nf < 4; nf++)
                    mma_tf32(acc[mf][nf], a[mf], b[nf]);
        }
    }

    #pragma unroll
    for (int mf = 0; mf < 4; mf++) {
        int row = mBase + wm * 64 + mf * 16 + lr;
        #pragma unroll
        for (int nf = 0; nf < 4; nf++) {
            int col = nBase + wn * 32 + nf * 8 + lc * 2;
            float2 v0 = {acc[mf][nf][0], acc[mf][nf][1]};
            float2 v1 = {acc[mf][nf][2], acc[mf][nf][3]};
            *(float2*)(C + (size_t)row * N + col)       = v0;
            *(float2*)(C + (size_t)(row + 8) * N + col) = v1;
        }
    }
}

// ---------------------------------------------------------------------------
// RMS-norm q and k rows in-place inside qkv
// ---------------------------------------------------------------------------
__global__ void __launch_bounds__(256) rmsnorm_qk(float* __restrict__ qkv)
{
    int gw = (blockIdx.x * blockDim.x + threadIdx.x) >> 5;
    int lane = threadIdx.x & 31;
    const int total = BB * SS * HH * 2;
    if (gw >= total) return;
    int which = gw & 1;
    int t = gw >> 1;
    int h = t % HH;
    int bs = t / HH;
    float* p = qkv + (size_t)bs * F3D + which * DD + h * HD + lane * 4;
    float4 v = *(float4*)p;
    float ss = v.x*v.x + v.y*v.y + v.z*v.z + v.w*v.w;
    #pragma unroll
    for (int off = 16; off; off >>= 1) ss += __shfl_xor_sync(0xffffffffu, ss, off);
    float r = rsqrtf(ss * (1.f / HD) + 1e-6f);
    v.x *= r; v.y *= r; v.z *= r; v.w *= r;
    *(float4*)p = v;
}

// ---------------------------------------------------------------------------
// Tensor-core causal flash attention v2.
// K pre-split into (hi,lo) tf32 pairs at staging; big-qb-first block order.
// smem: Qs fp32[128][132] | Khl uint2[64][132] | Vt u32[128][68] | Ps u32[128][68]
// ---------------------------------------------------------------------------
#define QS_ST 132
#define KHL_ST 132
#define PS_ST 68
#define ATT_SMEM (128*132*4 + 64*132*8 + 128*68*4 + 128*68*4)

__global__ void __launch_bounds__(256) flash_attn_tc(
    const float* __restrict__ qkv, float* __restrict__ out)
{
    char* smem = dyn_smem;
    float* Qs = (float*)smem;                                    // [128][132]
    uint2* Khl = (uint2*)(smem + 128*132*4);                     // [64][132]
    unsigned* Vt = (unsigned*)(smem + 128*132*4 + 64*132*8);     // [128][68]
    unsigned* Ps = (unsigned*)(smem + 128*132*4 + 64*132*8 + 128*68*4); // [128][68]

    int tid = threadIdx.x, lane = tid & 31, wid = tid >> 5;
    int lr = lane >> 2, lc = lane & 3;
    int b = blockIdx.z, h = blockIdx.y;
    int qb = (int)gridDim.x - 1 - (int)blockIdx.x;   // big tiles first
    int wrow = wid * 16;

    const float scale = 0.08838834764831845f;  // 1/sqrt(128)

    // ---- stage Q tile (fp32) ----
    {
        const float* qbase = qkv + ((size_t)(b * SS + qb * 128)) * F3D + h * HD;
        #pragma unroll
        for (int j = 0; j < 16; j++) {
            int lin = j * 256 + tid;
            int row = lin >> 5, q = (lin & 31) * 4;
            *(float4*)&Qs[row * QS_ST + q] = *(const float4*)(qbase + (size_t)row * F3D + q);
        }
    }

    float o[16][4];
    #pragma unroll
    for (int i = 0; i < 16; i++)
        #pragma unroll
        for (int j = 0; j < 4; j++) o[i][j] = 0.f;
    float m0 = -INFINITY, m1 = -INFINITY, l0 = 0.f, l1 = 0.f;

    int gr0 = qb * 128 + wrow + lr;
    int kEnd = (qb + 1) * 128;

    for (int k0 = 0; k0 < kEnd; k0 += 64) {
        __syncthreads();
        // ---- stage K as (hi,lo) tf32 pairs, V as tf32 transposed ----
        {
            const float* kbase = qkv + ((size_t)(b * SS + k0)) * F3D + DD + h * HD;
            #pragma unroll
            for (int j = 0; j < 8; j++) {
                int lin = j * 256 + tid;
                int row = lin >> 5, q = (lin & 31) * 4;
                float4 v = *(const float4*)(kbase + (size_t)row * F3D + q);
                unsigned hx = f2tf32(v.x), hy = f2tf32(v.y);
                unsigned hz = f2tf32(v.z), hw = f2tf32(v.w);
                uint4 p0 = {hx, f2tf32(v.x - __uint_as_float(hx)),
                            hy, f2tf32(v.y - __uint_as_float(hy))};
                uint4 p1 = {hz, f2tf32(v.z - __uint_as_float(hz)),
                            hw, f2tf32(v.w - __uint_as_float(hw))};
                *(uint4*)&Khl[row * KHL_ST + q]     = p0;
                *(uint4*)&Khl[row * KHL_ST + q + 2] = p1;
            }
            const float* vbase = qkv + ((size_t)(b * SS + k0)) * F3D + 2 * DD + h * HD;
            #pragma unroll
            for (int j = 0; j < 8; j++) {
                int lin = j * 256 + tid;
                int key = lin & 63, ch = lin >> 6;
                float4 v = *(const float4*)(vbase + (size_t)key * F3D + ch * 4);
                Vt[(ch * 4 + 0) * PS_ST + key] = f2tf32(v.x);
                Vt[(ch * 4 + 1) * PS_ST + key] = f2tf32(v.y);
                Vt[(ch * 4 + 2) * PS_ST + key] = f2tf32(v.z);
                Vt[(ch * 4 + 3) * PS_ST + key] = f2tf32(v.w);
            }
        }
        __syncthreads();

        // ---- S = Q K^T (3xTF32, K pre-split) ----
        float s[8][4];
        #pragma unroll
        for (int nf = 0; nf < 8; nf++)
            #pragma unroll
            for (int j = 0; j < 4; j++) s[nf][j] = 0.f;

        #pragma unroll
        for (int ks = 0; ks < 16; ks++) {
            int c = ks * 8 + lc;
            float af[4];
            af[0] = Qs[(wrow + lr) * QS_ST + c];
            af[1] = Qs[(wrow + lr + 8) * QS_ST + c];
            af[2] = Qs[(wrow + lr) * QS_ST + c + 4];
            af[3] = Qs[(wrow + lr + 8) * QS_ST + c + 4];
            unsigned ah[4], al[4];
            #pragma unroll
            for (int i = 0; i < 4; i++) {
                ah[i] = f2tf32(af[i]);
                al[i] = f2tf32(af[i] - __uint_as_float(ah[i]));
            }
            #pragma unroll
            for (int nf = 0; nf < 8; nf++) {
                uint2 k0v = Khl[(nf * 8 + lr) * KHL_ST + c];
                uint2 k1v = Khl[(nf * 8 + lr) * KHL_ST + c + 4];
                unsigned bh[2] = {k0v.x, k1v.x};
                unsigned bl[2] = {k0v.y, k1v.y};
                mma_tf32(s[nf], ah, bh);
                mma_tf32(s[nf], ah, bl);
                mma_tf32(s[nf], al, bh);
            }
        }

        // ---- scale + causal mask ----
        #pragma unroll
        for (int nf = 0; nf < 8; nf++) {
            int c0 = k0 + nf * 8 + lc * 2;
            s[nf][0] = (c0     > gr0)     ? -INFINITY : s[nf][0] * scale;
            s[nf][1] = (c0 + 1 > gr0)     ? -INFINITY : s[nf][1] * scale;
            s[nf][2] = (c0     > gr0 + 8) ? -INFINITY : s[nf][2] * scale;
            s[nf][3] = (c0 + 1 > gr0 + 8) ? -INFINITY : s[nf][3] * scale;
        }

        // ---- online softmax ----
        float mn0 = m0, mn1 = m1;
        #pragma unroll
        for (int nf = 0; nf < 8; nf++) {
            mn0 = fmaxf(mn0, fmaxf(s[nf][0], s[nf][1]));
            mn1 = fmaxf(mn1, fmaxf(s[nf][2], s[nf][3]));
        }
        mn0 = fmaxf(mn0, __shfl_xor_sync(0xffffffffu, mn0, 1));
        mn0 = fmaxf(mn0, __shfl_xor_sync(0xffffffffu, mn0, 2));
        mn1 = fmaxf(mn1, __shfl_xor_sync(0xffffffffu, mn1, 1));
        mn1 = fmaxf(mn1, __shfl_xor_sync(0xffffffffu, mn1, 2));

        float corr0 = __expf(m0 - mn0), corr1 = __expf(m1 - mn1);
        m0 = mn0; m1 = mn1;

        float ps0 = 0.f, ps1 = 0.f;
        #pragma unroll
        for (int nf = 0; nf < 8; nf++) {
            float p0 = __expf(s[nf][0] - mn0);
            float p1 = __expf(s[nf][1] - mn0);
            float p2 = __expf(s[nf][2] - mn1);
            float p3 = __expf(s[nf][3] - mn1);
            ps0 += p0 + p1; ps1 += p2 + p3;
            int col = nf * 8 + lc * 2;
            Ps[(wrow + lr) * PS_ST + col]         = f2tf32(p0);
            Ps[(wrow + lr) * PS_ST + col + 1]     = f2tf32(p1);
            Ps[(wrow + lr + 8) * PS_ST + col]     = f2tf32(p2);
            Ps[(wrow + lr + 8) * PS_ST + col + 1] = f2tf32(p3);
        }
        ps0 += __shfl_xor_sync(0xffffffffu, ps0, 1);
        ps0 += __shfl_xor_sync(0xffffffffu, ps0, 2);
        ps1 += __shfl_xor_sync(0xffffffffu, ps1, 1);
        ps1 += __shfl_xor_sync(0xffffffffu, ps1, 2);
        l0 = l0 * corr0 + ps0;
        l1 = l1 * corr1 + ps1;

        #pragma unroll
        for (int nf = 0; nf < 16; nf++) {
            o[nf][0] *= corr0; o[nf][1] *= corr0;
            o[nf][2] *= corr1; o[nf][3] *= corr1;
        }
        __syncwarp();

        // ---- O += P V (tf32) ----
        #pragma unroll
        for (int ks = 0; ks < 8; ks++) {
            int kk = ks * 8 + lc;
            unsigned a[4];
            a[0] = Ps[(wrow + lr) * PS_ST + kk];
            a[1] = Ps[(wrow + lr + 8) * PS_ST + kk];
            a[2] = Ps[(wrow + lr) * PS_ST + kk + 4];
            a[3] = Ps[(wrow + lr + 8) * PS_ST + kk + 4];
            #pragma unroll
            for (int nf = 0; nf < 16; nf++) {
                unsigned bv[2];
                bv[0] = Vt[(nf * 8 + lr) * PS_ST + kk];
                bv[1] = Vt[(nf * 8 + lr) * PS_ST + kk + 4];
                mma_tf32(o[nf], a, bv);
            }
        }
        __syncwarp();
    }

    // ---- epilogue: /l, rms_norm, write ----
    float il0 = 1.f / l0, il1 = 1.f / l1;
    float ss0 = 0.f, ss1 = 0.f;
    #pragma unroll
    for (int nf = 0; nf < 16; nf++) {
        o[nf][0] *= il0; o[nf][1] *= il0;
        o[nf][2] *= il1; o[nf][3] *= il1;
        ss0 += o[nf][0]*o[nf][0] + o[nf][1]*o[nf][1];
        ss1 += o[nf][2]*o[nf][2] + o[nf][3]*o[nf][3];
    }
    ss0 += __shfl_xor_sync(0xffffffffu, ss0, 1);
    ss0 += __shfl_xor_sync(0xffffffffu, ss0, 2);
    ss1 += __shfl_xor_sync(0xffffffffu, ss1, 1);
    ss1 += __shfl_xor_sync(0xffffffffu, ss1, 2);
    float rn0 = rsqrtf(ss0 * (1.f / HD) + 1e-6f);
    float rn1 = rsqrtf(ss1 * (1.f / HD) + 1e-6f);

    float* o0 = out + ((size_t)(b * SS + gr0)) * DD + h * HD;
    float* o1 = out + ((size_t)(b * SS + gr0 + 8)) * DD + h * HD;
    #pragma unroll
    for (int nf = 0; nf < 16; nf++) {
        int col = nf * 8 + lc * 2;
        float2 v0 = {o[nf][0] * rn0, o[nf][1] * rn0};
        float2 v1 = {o[nf][2] * rn1, o[nf][3] * rn1};
        *(float2*)(o0 + col) = v0;
        *(float2*)(o1 + col) = v1;
    }
}

// ---------------------------------------------------------------------------
extern "C" void kernel_launch(void* const* d_in, const int* in_sizes, int n_in,
                              void* d_out, int out_size)
{
    const float* x = nullptr; const float* w_in = nullptr; const float* w_out = nullptr;
    for (int i = 0; i < n_in; i++) {
        if (in_sizes[i] == BB * SS * DD)      x     = (const float*)d_in[i];
        else if (in_sizes[i] == F3D * DD)     w_in  = (const float*)d_in[i];
        else if (in_sizes[i] == DD * DD)      w_out = (const float*)d_in[i];
    }

    float* win_n;  cudaGetSymbolAddress((void**)&win_n, g_win_n);
    float* wout_n; cudaGetSymbolAddress((void**)&wout_n, g_wout_n);
    float* qkv;    cudaGetSymbolAddress((void**)&qkv, g_qkv);
    float* a;      cudaGetSymbolAddress((void**)&a, g_a);

    cudaFuncSetAttribute(gemm_tf32, cudaFuncAttributeMaxDynamicSharedMemorySize, GEMM_SMEM);
    cudaFuncSetAttribute(flash_attn_tc, cudaFuncAttributeMaxDynamicSharedMemorySize, ATT_SMEM);

    // 1) normalize weights
    unit_norm_rows<<<F3D, 256>>>(w_in, win_n, DD);
    unit_norm_rows<<<DD, 256>>>(w_out, wout_n, DD);

    // 2) qkv = x @ w_in_n^T : [8192,6144]
    {
        dim3 grid(F3D / 128, MROWS / 128);
        gemm_tf32<<<grid, 256, GEMM_SMEM>>>(x, win_n, qkv, MROWS, F3D, DD);
    }

    // 3) rms_norm q,k rows (in place)
    {
        int totalWarps = BB * SS * HH * 2;
        int blocks = (totalWarps * 32 + 255) / 256;
        rmsnorm_qk<<<blocks, 256>>>(qkv);
    }

    // 4) tensor-core flash attention + fused rms_norm -> g_a
    {
        dim3 grid(SS / 128, HH, BB);
        flash_attn_tc<<<grid, 256, ATT_SMEM>>>(qkv, a);
    }

    // 5) out = a @ w_out_n^T : [8192,2048]
    {
        dim3 grid(DD / 128, MROWS / 128);
        gemm_tf32<<<grid, 256, GEMM_SMEM>>>(a, wout_n, (float*)d_out, MROWS, DD, DD);
    }
}

// round 8
// speedup vs baseline: 15.2274x; 2.1223x over previous
#include <cuda_runtime.h>
#include <cuda_fp16.h>
#include <math.h>
#include <cstdint>

// Problem constants
#define BB 4
#define SS 2048
#define DD 2048
#define HH 16
#define HD 128
#define F3D (3*DD)          // 6144
#define MROWS (BB*SS)       // 8192

// Scratch (device globals; no allocation allowed)
__device__ __half g_xh[(size_t)MROWS * DD];     // x in half
__device__ __half g_win_h[(size_t)F3D * DD];    // normalized w_in, half
__device__ __half g_wout_h[(size_t)DD * DD];    // normalized w_out, half
__device__ float  g_qkv[(size_t)MROWS * F3D];   // qkv fp32
__device__ __half g_ah[(size_t)MROWS * DD];     // attn output (rms-normed), half

extern __shared__ __align__(16) char dyn_smem[];

// ---------------------------------------------------------------------------
__device__ __forceinline__ uint32_t smem_to_u32(const void* p) {
    uint32_t a;
    asm("{ .reg .u64 t; cvta.to.shared.u64 t, %1; cvt.u32.u64 %0, t; }" : "=r"(a) : "l"(p));
    return a;
}
__device__ __forceinline__ void cp_async16(uint32_t saddr, const void* gptr) {
    asm volatile("cp.async.cg.shared.global [%0], [%1], 16;" :: "r"(saddr), "l"(gptr));
}
#define CP_COMMIT() asm volatile("cp.async.commit_group;" ::: "memory")
#define CP_WAIT1()  asm volatile("cp.async.wait_group 1;" ::: "memory")

__device__ __forceinline__ void mma_f16(float* c, const unsigned* a, const unsigned* b) {
    asm volatile(
        "mma.sync.aligned.m16n8k16.row.col.f32.f16.f16.f32 "
        "{%0,%1,%2,%3}, {%4,%5,%6,%7}, {%8,%9}, {%0,%1,%2,%3};"
        : "+f"(c[0]), "+f"(c[1]), "+f"(c[2]), "+f"(c[3])
        : "r"(a[0]), "r"(a[1]), "r"(a[2]), "r"(a[3]), "r"(b[0]), "r"(b[1]));
}
__device__ __forceinline__ unsigned pack_h2(float lo, float hi) {
    __half2 h = __floats2half2_rn(lo, hi);
    return *(unsigned*)&h;
}

// ---------------------------------------------------------------------------
// x (fp32) -> half
// ---------------------------------------------------------------------------
__global__ void __launch_bounds__(256) cvt_f2h(const float* __restrict__ x,
                                               __half* __restrict__ xh)
{
    size_t i = ((size_t)blockIdx.x * 256 + threadIdx.x) * 4;
    float4 v = *(const float4*)(x + i);
    unsigned* o = (unsigned*)(xh + i);
    o[0] = pack_h2(v.x, v.y);
    o[1] = pack_h2(v.z, v.w);
}

// ---------------------------------------------------------------------------
// Row unit-normalize -> half output
// ---------------------------------------------------------------------------
__global__ void __launch_bounds__(256) unit_norm_rows_h(
    const float* __restrict__ w, __half* __restrict__ o, int cols)
{
    int row = blockIdx.x, tid = threadIdx.x;
    const float* src = w + (size_t)row * cols;
    __half* dst = o + (size_t)row * cols;
    float ss = 0.f;
    for (int i = tid * 4; i < cols; i += 1024) {
        float4 v = *(const float4*)(src + i);
        ss += v.x*v.x + v.y*v.y + v.z*v.z + v.w*v.w;
    }
    #pragma unroll
    for (int off = 16; off; off >>= 1) ss += __shfl_xor_sync(0xffffffffu, ss, off);
    __shared__ float red[8];
    if ((tid & 31) == 0) red[tid >> 5] = ss;
    __syncthreads();
    float total = 0.f;
    #pragma unroll
    for (int i = 0; i < 8; i++) total += red[i];
    float r = rsqrtf(total + 1e-6f);
    for (int i = tid * 4; i < cols; i += 1024) {
        float4 v = *(const float4*)(src + i);
        unsigned* op = (unsigned*)(dst + i);
        op[0] = pack_h2(v.x * r, v.y * r);
        op[1] = pack_h2(v.z * r, v.w * r);
    }
}

// ---------------------------------------------------------------------------
// FP16 tensor-core GEMM, 3-stage cp.async pipeline.
// C[m,n] = sum_k A[m,k]*B[n,k]; A: MxK half row-major, B: NxK half row-major.
// BM=BN=128, BK=32, 256 thr, 8 warps, warp tile 64x32, mma m16n8k16.
// smem: half, stride 40 (pad) -> conflict-free frag loads.
// Stage = 2 * 128*40*2 = 20480 B; 3 stages = 61440 B.
// ---------------------------------------------------------------------------
#define HBKP 40
#define HSTG_B 20480
#define GEMM_SMEM (3 * HSTG_B)

__global__ void __launch_bounds__(256, 2) gemm_fp16(
    const __half* __restrict__ A, const __half* __restrict__ B,
    float* __restrict__ C, int M, int N, int K)
{
    __half* smem = (__half*)dyn_smem;

    int tid = threadIdx.x, lane = tid & 31, warp = tid >> 5;
    int wm = warp >> 2, wn = warp & 3;
    int mBase = blockIdx.y * 128, nBase = blockIdx.x * 128;
    int lr = lane >> 2, lc = lane & 3;

    // global-load mapping: 512 16B-chunks per matrix, 2 per thread
    int r0 = tid >> 2, o0 = (tid & 3) * 8;     // rows 0..63
    const __half* Ap0 = A + (size_t)(mBase + r0) * K + o0;
    const __half* Ap1 = A + (size_t)(mBase + r0 + 64) * K + o0;
    const __half* Bp0 = B + (size_t)(nBase + r0) * K + o0;
    const __half* Bp1 = B + (size_t)(nBase + r0 + 64) * K + o0;

    uint32_t sb = smem_to_u32(smem);
    uint32_t sA0 = sb + (r0 * HBKP + o0) * 2;
    uint32_t sA1 = sb + ((r0 + 64) * HBKP + o0) * 2;
    uint32_t sB0 = sA0 + 128 * HBKP * 2;
    uint32_t sB1 = sA1 + 128 * HBKP * 2;

    float acc[4][4][4];
    #pragma unroll
    for (int i = 0; i < 4; i++)
        #pragma unroll
        for (int j = 0; j < 4; j++)
            #pragma unroll
            for (int l = 0; l < 4; l++) acc[i][j][l] = 0.f;

    const int T = K / 32;

    #pragma unroll
    for (int s = 0; s < 2; s++) {
        uint32_t so = s * HSTG_B;
        int k0 = s * 32;
        cp_async16(sA0 + so, Ap0 + k0);
        cp_async16(sA1 + so, Ap1 + k0);
        cp_async16(sB0 + so, Bp0 + k0);
        cp_async16(sB1 + so, Bp1 + k0);
        CP_COMMIT();
    }

    for (int t = 0; t < T; t++) {
        CP_WAIT1();
        __syncthreads();

        if (t + 2 < T) {
            uint32_t so = ((t + 2) % 3) * HSTG_B;
            int k0 = (t + 2) * 32;
            cp_async16(sA0 + so, Ap0 + k0);
            cp_async16(sA1 + so, Ap1 + k0);
            cp_async16(sB0 + so, Bp0 + k0);
            cp_async16(sB1 + so, Bp1 + k0);
        }
        CP_COMMIT();

        const __half* As = smem + (t % 3) * (HSTG_B / 2);
        const __half* Bs = As + 128 * HBKP;
        #pragma unroll
        for (int ch = 0; ch < 2; ch++) {          // two k16 chunks
            int c = ch * 16 + 2 * lc;
            unsigned a[4][4], b[4][2];
            #pragma unroll
            for (int mf = 0; mf < 4; mf++) {
                int r = wm * 64 + mf * 16 + lr;
                a[mf][0] = *(const unsigned*)(As + r * HBKP + c);
                a[mf][1] = *(const unsigned*)(As + (r + 8) * HBKP + c);
                a[mf][2] = *(const unsigned*)(As + r * HBKP + c + 8);
                a[mf][3] = *(const unsigned*)(As + (r + 8) * HBKP + c + 8);
            }
            #pragma unroll
            for (int nf = 0; nf < 4; nf++) {
                int n = wn * 32 + nf * 8 + lr;
                b[nf][0] = *(const unsigned*)(Bs + n * HBKP + c);
                b[nf][1] = *(const unsigned*)(Bs + n * HBKP + c + 8);
            }
            #pragma unroll
            for (int mf = 0; mf < 4; mf++)
                #pragma unroll
                for (int nf = 0; nf < 4; nf++)
                    mma_f16(acc[mf][nf], a[mf], b[nf]);
        }
    }

    #pragma unroll
    for (int mf = 0; mf < 4; mf++) {
        int row = mBase + wm * 64 + mf * 16 + lr;
        #pragma unroll
        for (int nf = 0; nf < 4; nf++) {
            int col = nBase + wn * 32 + nf * 8 + lc * 2;
            float2 v0 = {acc[mf][nf][0], acc[mf][nf][1]};
            float2 v1 = {acc[mf][nf][2], acc[mf][nf][3]};
            *(float2*)(C + (size_t)row * N + col)       = v0;
            *(float2*)(C + (size_t)(row + 8) * N + col) = v1;
        }
    }
}

// ---------------------------------------------------------------------------
// RMS-norm q and k rows in-place inside qkv (fp32)
// ---------------------------------------------------------------------------
__global__ void __launch_bounds__(256) rmsnorm_qk(float* __restrict__ qkv)
{
    int gw = (blockIdx.x * blockDim.x + threadIdx.x) >> 5;
    int lane = threadIdx.x & 31;
    const int total = BB * SS * HH * 2;
    if (gw >= total) return;
    int which = gw & 1;
    int t = gw >> 1;
    int h = t % HH;
    int bs = t / HH;
    float* p = qkv + (size_t)bs * F3D + which * DD + h * HD + lane * 4;
    float4 v = *(float4*)p;
    float ss = v.x*v.x + v.y*v.y + v.z*v.z + v.w*v.w;
    #pragma unroll
    for (int off = 16; off; off >>= 1) ss += __shfl_xor_sync(0xffffffffu, ss, off);
    float r = rsqrtf(ss * (1.f / HD) + 1e-6f);
    v.x *= r; v.y *= r; v.z *= r; v.w *= r;
    *(float4*)p = v;
}

// ---------------------------------------------------------------------------
// FP16 tensor-core causal flash attention.
// BM=128 q rows, BN=64 keys/iter, 8 warps; QK 3-term fp16 hi/lo; PV fp16 1x.
// smem (uints): Qh2[128][68] Ql2[128][68] Kh2[64][68] Kl2[64][68]
//               Vp[32][136] (key-pair major) Pp[128][36]
// ---------------------------------------------------------------------------
#define QST 68
#define KST 68
#define VST 136
#define PST 36
#define ATT_SMEM (128*QST*4*2 + 64*KST*4*2 + 32*VST*4 + 128*PST*4)

__global__ void __launch_bounds__(256) flash_attn_fp16(
    const float* __restrict__ qkv, __half* __restrict__ out)
{
    char* smem = dyn_smem;
    unsigned* Qh2 = (unsigned*)smem;                              // [128][68]
    unsigned* Ql2 = Qh2 + 128 * QST;
    unsigned* Kh2 = Ql2 + 128 * QST;                              // [64][68]
    unsigned* Kl2 = Kh2 + 64 * KST;
    unsigned* Vp  = Kl2 + 64 * KST;                               // [32][136]
    unsigned* Pp  = Vp + 32 * VST;                                // [128][36]

    int tid = threadIdx.x, lane = tid & 31, wid = tid >> 5;
    int lr = lane >> 2, lc = lane & 3;
    int b = blockIdx.z, h = blockIdx.y;
    int qb = (int)gridDim.x - 1 - (int)blockIdx.x;   // big tiles first
    int wrow = wid * 16;

    const float scale = 0.08838834764831845f;  // 1/sqrt(128)

    // ---- stage Q tile: split to (hi,lo) half2 ----
    {
        const float* qbase = qkv + ((size_t)(b * SS + qb * 128)) * F3D + h * HD;
        #pragma unroll
        for (int j = 0; j < 16; j++) {
            int lin = j * 256 + tid;
            int row = lin >> 5, d = (lin & 31) * 4;
            float4 v = *(const float4*)(qbase + (size_t)row * F3D + d);
            unsigned hxy = pack_h2(v.x, v.y), hzw = pack_h2(v.z, v.w);
            __half2 hh0 = *(__half2*)&hxy, hh1 = *(__half2*)&hzw;
            float2 f0 = __half22float2(hh0), f1 = __half22float2(hh1);
            Qh2[row * QST + d / 2]     = hxy;
            Qh2[row * QST + d / 2 + 1] = hzw;
            Ql2[row * QST + d / 2]     = pack_h2(v.x - f0.x, v.y - f0.y);
            Ql2[row * QST + d / 2 + 1] = pack_h2(v.z - f1.x, v.w - f1.y);
        }
    }

    float o[16][4];
    #pragma unroll
    for (int i = 0; i < 16; i++)
        #pragma unroll
        for (int j = 0; j < 4; j++) o[i][j] = 0.f;
    float m0 = -INFINITY, m1 = -INFINITY, l0 = 0.f, l1 = 0.f;

    int gr0 = qb * 128 + wrow + lr;
    int kEnd = (qb + 1) * 128;

    for (int k0 = 0; k0 < kEnd; k0 += 64) {
        __syncthreads();
        // ---- stage K (hi/lo half2) and V (key-pair half2) ----
        {
            const float* kbase = qkv + ((size_t)(b * SS + k0)) * F3D + DD + h * HD;
            #pragma unroll
            for (int j = 0; j < 8; j++) {
                int lin = j * 256 + tid;
                int row = lin >> 5, d = (lin & 31) * 4;
                float4 v = *(const float4*)(kbase + (size_t)row * F3D + d);
                unsigned hxy = pack_h2(v.x, v.y), hzw = pack_h2(v.z, v.w);
                __half2 hh0 = *(__half2*)&hxy, hh1 = *(__half2*)&hzw;
                float2 f0 = __half22float2(hh0), f1 = __half22float2(hh1);
                Kh2[row * KST + d / 2]     = hxy;
                Kh2[row * KST + d / 2 + 1] = hzw;
                Kl2[row * KST + d / 2]     = pack_h2(v.x - f0.x, v.y - f0.y);
                Kl2[row * KST + d / 2 + 1] = pack_h2(v.z - f1.x, v.w - f1.y);
            }
            const float* vbase = qkv + ((size_t)(b * SS + k0)) * F3D + 2 * DD + h * HD;
            #pragma unroll
            for (int j = 0; j < 4; j++) {
                int id = j * 256 + tid;              // 1024 assignments
                int key2 = id >> 5, d = (id & 31) * 4;
                const float* p0 = vbase + (size_t)(2 * key2) * F3D + d;
                float4 va = *(const float4*)p0;
                float4 vb = *(const float4*)(p0 + F3D);
                Vp[key2 * VST + d]     = pack_h2(va.x, vb.x);
                Vp[key2 * VST + d + 1] = pack_h2(va.y, vb.y);
                Vp[key2 * VST + d + 2] = pack_h2(va.z, vb.z);
                Vp[key2 * VST + d + 3] = pack_h2(va.w, vb.w);
            }
        }
        __syncthreads();

        // ---- S = Q K^T : 3-term fp16 (qh*kh + qh*kl + ql*kh) ----
        float s[8][4];
        #pragma unroll
        for (int nf = 0; nf < 8; nf++)
            #pragma unroll
            for (int j = 0; j < 4; j++) s[nf][j] = 0.f;

        #pragma unroll
        for (int ks = 0; ks < 8; ks++) {             // 8 k16-chunks over hd=128
            int d2 = lc + 8 * ks;
            unsigned ah[4], al[4];
            int r = wrow + lr;
            ah[0] = Qh2[r * QST + d2];       ah[1] = Qh2[(r + 8) * QST + d2];
            ah[2] = Qh2[r * QST + d2 + 4];   ah[3] = Qh2[(r + 8) * QST + d2 + 4];
            al[0] = Ql2[r * QST + d2];       al[1] = Ql2[(r + 8) * QST + d2];
            al[2] = Ql2[r * QST + d2 + 4];   al[3] = Ql2[(r + 8) * QST + d2 + 4];
            #pragma unroll
            for (int nf = 0; nf < 8; nf++) {
                int n = nf * 8 + lr;
                unsigned bh[2], bl[2];
                bh[0] = Kh2[n * KST + d2];   bh[1] = Kh2[n * KST + d2 + 4];
                bl[0] = Kl2[n * KST + d2];   bl[1] = Kl2[n * KST + d2 + 4];
                mma_f16(s[nf], ah, bh);
                mma_f16(s[nf], ah, bl);
                mma_f16(s[nf], al, bh);
            }
        }

        // ---- scale + causal mask ----
        #pragma unroll
        for (int nf = 0; nf < 8; nf++) {
            int c0 = k0 + nf * 8 + lc * 2;
            s[nf][0] = (c0     > gr0)     ? -INFINITY : s[nf][0] * scale;
            s[nf][1] = (c0 + 1 > gr0)     ? -INFINITY : s[nf][1] * scale;
            s[nf][2] = (c0     > gr0 + 8) ? -INFINITY : s[nf][2] * scale;
            s[nf][3] = (c0 + 1 > gr0 + 8) ? -INFINITY : s[nf][3] * scale;
        }

        // ---- online softmax ----
        float mn0 = m0, mn1 = m1;
        #pragma unroll
        for (int nf = 0; nf < 8; nf++) {
            mn0 = fmaxf(mn0, fmaxf(s[nf][0], s[nf][1]));
            mn1 = fmaxf(mn1, fmaxf(s[nf][2], s[nf][3]));
        }
        mn0 = fmaxf(mn0, __shfl_xor_sync(0xffffffffu, mn0, 1));
        mn0 = fmaxf(mn0, __shfl_xor_sync(0xffffffffu, mn0, 2));
        mn1 = fmaxf(mn1, __shfl_xor_sync(0xffffffffu, mn1, 1));
        mn1 = fmaxf(mn1, __shfl_xor_sync(0xffffffffu, mn1, 2));

        float corr0 = __expf(m0 - mn0), corr1 = __expf(m1 - mn1);
        m0 = mn0; m1 = mn1;

        float ps0 = 0.f, ps1 = 0.f;
        int r = wrow + lr;
        #pragma unroll
        for (int nf = 0; nf < 8; nf++) {
            float p0 = __expf(s[nf][0] - mn0);
            float p1 = __expf(s[nf][1] - mn0);
            float p2 = __expf(s[nf][2] - mn1);
            float p3 = __expf(s[nf][3] - mn1);
            ps0 += p0 + p1; ps1 += p2 + p3;
            int key2 = nf * 4 + lc;
            Pp[r * PST + key2]       = pack_h2(p0, p1);
            Pp[(r + 8) * PST + key2] = pack_h2(p2, p3);
        }
        ps0 += __shfl_xor_sync(0xffffffffu, ps0, 1);
        ps0 += __shfl_xor_sync(0xffffffffu, ps0, 2);
        ps1 += __shfl_xor_sync(0xffffffffu, ps1, 1);
        ps1 += __shfl_xor_sync(0xffffffffu, ps1, 2);
        l0 = l0 * corr0 + ps0;
        l1 = l1 * corr1 + ps1;

        #pragma unroll
        for (int nf = 0; nf < 16; nf++) {
            o[nf][0] *= corr0; o[nf][1] *= corr0;
            o[nf][2] *= corr1; o[nf][3] *= corr1;
        }
        __syncwarp();

        // ---- O += P V (fp16) ----
        #pragma unroll
        for (int ks = 0; ks < 4; ks++) {             // 4 k16-chunks over 64 keys
            int k2 = lc + 8 * ks;
            unsigned a[4];
            a[0] = Pp[r * PST + k2];        a[1] = Pp[(r + 8) * PST + k2];
            a[2] = Pp[r * PST + k2 + 4];    a[3] = Pp[(r + 8) * PST + k2 + 4];
            #pragma unroll
            for (int nf = 0; nf < 16; nf++) {
                int n = nf * 8 + lr;
                unsigned bv[2];
                bv[0] = Vp[k2 * VST + n];
                bv[1] = Vp[(k2 + 4) * VST + n];
                mma_f16(o[nf], a, bv);
            }
        }
        __syncwarp();
    }

    // ---- epilogue: /l, rms_norm, write half ----
    float il0 = 1.f / l0, il1 = 1.f / l1;
    float ss0 = 0.f, ss1 = 0.f;
    #pragma unroll
    for (int nf = 0; nf < 16; nf++) {
        o[nf][0] *= il0; o[nf][1] *= il0;
        o[nf][2] *= il1; o[nf][3] *= il1;
        ss0 += o[nf][0]*o[nf][0] + o[nf][1]*o[nf][1];
        ss1 += o[nf][2]*o[nf][2] + o[nf][3]*o[nf][3];
    }
    ss0 += __shfl_xor_sync(0xffffffffu, ss0, 1);
    ss0 += __shfl_xor_sync(0xffffffffu, ss0, 2);
    ss1 += __shfl_xor_sync(0xffffffffu, ss1, 1);
    ss1 += __shfl_xor_sync(0xffffffffu, ss1, 2);
    float rn0 = rsqrtf(ss0 * (1.f / HD) + 1e-6f);
    float rn1 = rsqrtf(ss1 * (1.f / HD) + 1e-6f);

    __half* o0 = out + ((size_t)(b * SS + gr0)) * DD + h * HD;
    __half* o1 = out + ((size_t)(b * SS + gr0 + 8)) * DD + h * HD;
    #pragma unroll
    for (int nf = 0; nf < 16; nf++) {
        int col = nf * 8 + lc * 2;
        *(unsigned*)(o0 + col) = pack_h2(o[nf][0] * rn0, o[nf][1] * rn0);
        *(unsigned*)(o1 + col) = pack_h2(o[nf][2] * rn1, o[nf][3] * rn1);
    }
}

// ---------------------------------------------------------------------------
extern "C" void kernel_launch(void* const* d_in, const int* in_sizes, int n_in,
                              void* d_out, int out_size)
{
    const float* x = nullptr; const float* w_in = nullptr; const float* w_out = nullptr;
    for (int i = 0; i < n_in; i++) {
        if (in_sizes[i] == BB * SS * DD)      x     = (const float*)d_in[i];
        else if (in_sizes[i] == F3D * DD)     w_in  = (const float*)d_in[i];
        else if (in_sizes[i] == DD * DD)      w_out = (const float*)d_in[i];
    }

    __half* xh;     cudaGetSymbolAddress((void**)&xh, g_xh);
    __half* win_h;  cudaGetSymbolAddress((void**)&win_h, g_win_h);
    __half* wout_h; cudaGetSymbolAddress((void**)&wout_h, g_wout_h);
    float*  qkv;    cudaGetSymbolAddress((void**)&qkv, g_qkv);
    __half* ah;     cudaGetSymbolAddress((void**)&ah, g_ah);

    cudaFuncSetAttribute(gemm_fp16, cudaFuncAttributeMaxDynamicSharedMemorySize, GEMM_SMEM);
    cudaFuncSetAttribute(flash_attn_fp16, cudaFuncAttributeMaxDynamicSharedMemorySize, ATT_SMEM);

    // 1) convert x to half; normalize weights to half
    cvt_f2h<<<(MROWS * DD) / 1024, 256>>>(x, xh);
    unit_norm_rows_h<<<F3D, 256>>>(w_in, win_h, DD);
    unit_norm_rows_h<<<DD, 256>>>(w_out, wout_h, DD);

    // 2) qkv = x @ w_in_n^T : [8192,6144] (fp16 mma)
    {
        dim3 grid(F3D / 128, MROWS / 128);
        gemm_fp16<<<grid, 256, GEMM_SMEM>>>(xh, win_h, qkv, MROWS, F3D, DD);
    }

    // 3) rms_norm q,k rows (in place, fp32)
    {
        int totalWarps = BB * SS * HH * 2;
        int blocks = (totalWarps * 32 + 255) / 256;
        rmsnorm_qk<<<blocks, 256>>>(qkv);
    }

    // 4) fp16 flash attention + fused rms_norm -> g_ah (half)
    {
        dim3 grid(SS / 128, HH, BB);
        flash_attn_fp16<<<grid, 256, ATT_SMEM>>>(qkv, ah);
    }

    // 5) out = a @ w_out_n^T : [8192,2048] (fp16 mma, fp32 out)
    {
        dim3 grid(DD / 128, MROWS / 128);
        gemm_fp16<<<grid, 256, GEMM_SMEM>>>(ah, wout_h, (float*)d_out, MROWS, DD, DD);
    }
}

// round 9
// speedup vs baseline: 16.1349x; 1.0596x over previous
#include <cuda_runtime.h>
#include <cuda_fp16.h>
#include <math.h>
#include <cstdint>

// Problem constants
#define BB 4
#define SS 2048
#define DD 2048
#define HH 16
#define HD 128
#define F3D (3*DD)          // 6144
#define MROWS (BB*SS)       // 8192

// Scratch (device globals; no allocation allowed)
__device__ __half g_xh[(size_t)MROWS * DD];
__device__ __half g_win_h[(size_t)F3D * DD];
__device__ __half g_wout_h[(size_t)DD * DD];
__device__ float  g_qkv[(size_t)MROWS * F3D];
__device__ __half g_ah[(size_t)MROWS * DD];

extern __shared__ __align__(16) char dyn_smem[];

// ---------------------------------------------------------------------------
__device__ __forceinline__ uint32_t smem_to_u32(const void* p) {
    uint32_t a;
    asm("{ .reg .u64 t; cvta.to.shared.u64 t, %1; cvt.u32.u64 %0, t; }" : "=r"(a) : "l"(p));
    return a;
}
__device__ __forceinline__ void cp_async16(uint32_t saddr, const void* gptr) {
    asm volatile("cp.async.cg.shared.global [%0], [%1], 16;" :: "r"(saddr), "l"(gptr));
}
#define CP_COMMIT() asm volatile("cp.async.commit_group;" ::: "memory")
#define CP_WAIT1()  asm volatile("cp.async.wait_group 1;" ::: "memory")

__device__ __forceinline__ void mma_f16(float* c, const unsigned* a, const unsigned* b) {
    asm volatile(
        "mma.sync.aligned.m16n8k16.row.col.f32.f16.f16.f32 "
        "{%0,%1,%2,%3}, {%4,%5,%6,%7}, {%8,%9}, {%0,%1,%2,%3};"
        : "+f"(c[0]), "+f"(c[1]), "+f"(c[2]), "+f"(c[3])
        : "r"(a[0]), "r"(a[1]), "r"(a[2]), "r"(a[3]), "r"(b[0]), "r"(b[1]));
}
__device__ __forceinline__ void ldsm_x4(unsigned& r0, unsigned& r1, unsigned& r2,
                                        unsigned& r3, uint32_t addr) {
    asm volatile("ldmatrix.sync.aligned.m8n8.x4.shared.b16 {%0,%1,%2,%3}, [%4];"
        : "=r"(r0), "=r"(r1), "=r"(r2), "=r"(r3) : "r"(addr));
}
__device__ __forceinline__ unsigned pack_h2(float lo, float hi) {
    __half2 h = __floats2half2_rn(lo, hi);
    return *(unsigned*)&h;
}

// ---------------------------------------------------------------------------
__global__ void __launch_bounds__(256) cvt_f2h(const float* __restrict__ x,
                                               __half* __restrict__ xh)
{
    size_t i = ((size_t)blockIdx.x * 256 + threadIdx.x) * 4;
    float4 v = *(const float4*)(x + i);
    unsigned* o = (unsigned*)(xh + i);
    o[0] = pack_h2(v.x, v.y);
    o[1] = pack_h2(v.z, v.w);
}

// ---------------------------------------------------------------------------
__global__ void __launch_bounds__(256) unit_norm_rows_h(
    const float* __restrict__ w, __half* __restrict__ o, int cols)
{
    int row = blockIdx.x, tid = threadIdx.x;
    const float* src = w + (size_t)row * cols;
    __half* dst = o + (size_t)row * cols;
    float ss = 0.f;
    for (int i = tid * 4; i < cols; i += 1024) {
        float4 v = *(const float4*)(src + i);
        ss += v.x*v.x + v.y*v.y + v.z*v.z + v.w*v.w;
    }
    #pragma unroll
    for (int off = 16; off; off >>= 1) ss += __shfl_xor_sync(0xffffffffu, ss, off);
    __shared__ float red[8];
    if ((tid & 31) == 0) red[tid >> 5] = ss;
    __syncthreads();
    float total = 0.f;
    #pragma unroll
    for (int i = 0; i < 8; i++) total += red[i];
    float r = rsqrtf(total + 1e-6f);
    for (int i = tid * 4; i < cols; i += 1024) {
        float4 v = *(const float4*)(src + i);
        unsigned* op = (unsigned*)(dst + i);
        op[0] = pack_h2(v.x * r, v.y * r);
        op[1] = pack_h2(v.z * r, v.w * r);
    }
}

// ---------------------------------------------------------------------------
// FP16 GEMM, 3-stage cp.async pipeline + ldmatrix fragment loads.
// ---------------------------------------------------------------------------
#define HBKP 40
#define HSTG_B 20480
#define GEMM_SMEM (3 * HSTG_B)

__global__ void __launch_bounds__(256, 2) gemm_fp16(
    const __half* __restrict__ A, const __half* __restrict__ B,
    float* __restrict__ C, int M, int N, int K)
{
    __half* smem = (__half*)dyn_smem;

    int tid = threadIdx.x, lane = tid & 31, warp = tid >> 5;
    int wm = warp >> 2, wn = warp & 3;
    int mBase = blockIdx.y * 128, nBase = blockIdx.x * 128;
    int lr = lane >> 2, lc = lane & 3;
    int l7 = lane & 7, l8 = (lane >> 3) & 1, l16 = lane >> 4;

    int r0 = tid >> 2, o0 = (tid & 3) * 8;
    const __half* Ap0 = A + (size_t)(mBase + r0) * K + o0;
    const __half* Ap1 = A + (size_t)(mBase + r0 + 64) * K + o0;
    const __half* Bp0 = B + (size_t)(nBase + r0) * K + o0;
    const __half* Bp1 = B + (size_t)(nBase + r0 + 64) * K + o0;

    uint32_t sb = smem_to_u32(smem);
    uint32_t sA0 = sb + (r0 * HBKP + o0) * 2;
    uint32_t sA1 = sb + ((r0 + 64) * HBKP + o0) * 2;
    uint32_t sB0 = sA0 + 128 * HBKP * 2;
    uint32_t sB1 = sA1 + 128 * HBKP * 2;

    // ldmatrix per-lane offsets (bytes)
    uint32_t aOff[4], bOff[2];
    #pragma unroll
    for (int mf = 0; mf < 4; mf++)
        aOff[mf] = ((wm * 64 + mf * 16 + l7 + l8 * 8) * HBKP + l16 * 8) * 2;
    #pragma unroll
    for (int nfp = 0; nfp < 2; nfp++)
        bOff[nfp] = ((wn * 32 + nfp * 16 + l16 * 8 + l7) * HBKP + l8 * 8) * 2;

    float acc[4][4][4];
    #pragma unroll
    for (int i = 0; i < 4; i++)
        #pragma unroll
        for (int j = 0; j < 4; j++)
            #pragma unroll
            for (int l = 0; l < 4; l++) acc[i][j][l] = 0.f;

    const int T = K / 32;

    #pragma unroll
    for (int s = 0; s < 2; s++) {
        uint32_t so = s * HSTG_B;
        int k0 = s * 32;
        cp_async16(sA0 + so, Ap0 + k0);
        cp_async16(sA1 + so, Ap1 + k0);
        cp_async16(sB0 + so, Bp0 + k0);
        cp_async16(sB1 + so, Bp1 + k0);
        CP_COMMIT();
    }

    for (int t = 0; t < T; t++) {
        CP_WAIT1();
        __syncthreads();

        if (t + 2 < T) {
            uint32_t so = ((t + 2) % 3) * HSTG_B;
            int k0 = (t + 2) * 32;
            cp_async16(sA0 + so, Ap0 + k0);
            cp_async16(sA1 + so, Ap1 + k0);
            cp_async16(sB0 + so, Bp0 + k0);
            cp_async16(sB1 + so, Bp1 + k0);
        }
        CP_COMMIT();

        uint32_t sS = sb + (t % 3) * HSTG_B;
        uint32_t sBB = sS + 128 * HBKP * 2;
        #pragma unroll
        for (int ch = 0; ch < 2; ch++) {
            uint32_t cB = ch * 32;            // 16 halfwords
            unsigned a[4][4], b[4][2];
            #pragma unroll
            for (int mf = 0; mf < 4; mf++)
                ldsm_x4(a[mf][0], a[mf][1], a[mf][2], a[mf][3], sS + aOff[mf] + cB);
            #pragma unroll
            for (int nfp = 0; nfp < 2; nfp++) {
                unsigned q0, q1, q2, q3;
                ldsm_x4(q0, q1, q2, q3, sBB + bOff[nfp] + cB);
                b[2*nfp][0] = q0; b[2*nfp][1] = q1;
                b[2*nfp+1][0] = q2; b[2*nfp+1][1] = q3;
            }
            #pragma unroll
            for (int mf = 0; mf < 4; mf++)
                #pragma unroll
                for (int nf = 0; nf < 4; nf++)
                    mma_f16(acc[mf][nf], a[mf], b[nf]);
        }
    }

    #pragma unroll
    for (int mf = 0; mf < 4; mf++) {
        int row = mBase + wm * 64 + mf * 16 + lr;
        #pragma unroll
        for (int nf = 0; nf < 4; nf++) {
            int col = nBase + wn * 32 + nf * 8 + lc * 2;
            float2 v0 = {acc[mf][nf][0], acc[mf][nf][1]};
            float2 v1 = {acc[mf][nf][2], acc[mf][nf][3]};
            *(float2*)(C + (size_t)row * N + col)       = v0;
            *(float2*)(C + (size_t)(row + 8) * N + col) = v1;
        }
    }
}

// ---------------------------------------------------------------------------
__global__ void __launch_bounds__(256) rmsnorm_qk(float* __restrict__ qkv)
{
    int gw = (blockIdx.x * blockDim.x + threadIdx.x) >> 5;
    int lane = threadIdx.x & 31;
    const int total = BB * SS * HH * 2;
    if (gw >= total) return;
    int which = gw & 1;
    int t = gw >> 1;
    int h = t % HH;
    int bs = t / HH;
    float* p = qkv + (size_t)bs * F3D + which * DD + h * HD + lane * 4;
    float4 v = *(float4*)p;
    float ss = v.x*v.x + v.y*v.y + v.z*v.z + v.w*v.w;
    #pragma unroll
    for (int off = 16; off; off >>= 1) ss += __shfl_xor_sync(0xffffffffu, ss, off);
    float r = rsqrtf(ss * (1.f / HD) + 1e-6f);
    v.x *= r; v.y *= r; v.z *= r; v.w *= r;
    *(float4*)p = v;
}

// ---------------------------------------------------------------------------
// FP16 flash attention with ldmatrix fragment loads.
// smem (uints): Qh2[128][68] Ql2[128][68] Kh2[64][68] Kl2[64][68]
//               Vt[128][36] (dim-major, key-pair packed) Pp[128][36]
// ---------------------------------------------------------------------------
#define QST 68
#define KST 68
#define VST2 36
#define PST 36
#define ATT_SMEM ((128*QST*2 + 64*KST*2 + 128*VST2 + 128*PST) * 4)

__global__ void __launch_bounds__(256) flash_attn_fp16(
    const float* __restrict__ qkv, __half* __restrict__ out)
{
    unsigned* Qh2 = (unsigned*)dyn_smem;
    unsigned* Ql2 = Qh2 + 128 * QST;
    unsigned* Kh2 = Ql2 + 128 * QST;
    unsigned* Kl2 = Kh2 + 64 * KST;
    unsigned* Vt  = Kl2 + 64 * KST;
    unsigned* Pp  = Vt + 128 * VST2;

    int tid = threadIdx.x, lane = tid & 31, wid = tid >> 5;
    int lr = lane >> 2, lc = lane & 3;
    int l7 = lane & 7, l8 = (lane >> 3) & 1, l16 = lane >> 4;
    int b = blockIdx.z, h = blockIdx.y;
    int qb = (int)gridDim.x - 1 - (int)blockIdx.x;
    int wrow = wid * 16;

    uint32_t uQh = smem_to_u32(Qh2);
    uint32_t uQl = smem_to_u32(Ql2);
    uint32_t uKh = smem_to_u32(Kh2);
    uint32_t uKl = smem_to_u32(Kl2);
    uint32_t uVt = smem_to_u32(Vt);
    uint32_t uPp = smem_to_u32(Pp);

    // ldmatrix per-lane offsets (bytes)
    uint32_t qOff = ((wrow + l7 + l8 * 8) * QST + l16 * 4) * 4;
    uint32_t pOff = ((wrow + l7 + l8 * 8) * PST + l16 * 4) * 4;
    uint32_t kOff[4], vOff[8];
    #pragma unroll
    for (int nfp = 0; nfp < 4; nfp++)
        kOff[nfp] = ((nfp * 16 + l16 * 8 + l7) * KST + l8 * 4) * 4;
    #pragma unroll
    for (int nfp = 0; nfp < 8; nfp++)
        vOff[nfp] = ((nfp * 16 + l16 * 8 + l7) * VST2 + l8 * 4) * 4;

    const float scale = 0.08838834764831845f;

    // ---- stage Q (hi/lo half2) ----
    {
        const float* qbase = qkv + ((size_t)(b * SS + qb * 128)) * F3D + h * HD;
        #pragma unroll
        for (int j = 0; j < 16; j++) {
            int lin = j * 256 + tid;
            int row = lin >> 5, d = (lin & 31) * 4;
            float4 v = *(const float4*)(qbase + (size_t)row * F3D + d);
            unsigned hxy = pack_h2(v.x, v.y), hzw = pack_h2(v.z, v.w);
            __half2 hh0 = *(__half2*)&hxy, hh1 = *(__half2*)&hzw;
            float2 f0 = __half22float2(hh0), f1 = __half22float2(hh1);
            Qh2[row * QST + d / 2]     = hxy;
            Qh2[row * QST + d / 2 + 1] = hzw;
            Ql2[row * QST + d / 2]     = pack_h2(v.x - f0.x, v.y - f0.y);
            Ql2[row * QST + d / 2 + 1] = pack_h2(v.z - f1.x, v.w - f1.y);
        }
    }

    float o[16][4];
    #pragma unroll
    for (int i = 0; i < 16; i++)
        #pragma unroll
        for (int j = 0; j < 4; j++) o[i][j] = 0.f;
    float m0 = -INFINITY, m1 = -INFINITY, l0 = 0.f, l1 = 0.f;

    int gr0 = qb * 128 + wrow + lr;
    int kEnd = (qb + 1) * 128;

    for (int k0 = 0; k0 < kEnd; k0 += 64) {
        __syncthreads();
        // ---- stage K (hi/lo) and V (dim-major key-pair) ----
        {
            const float* kbase = qkv + ((size_t)(b * SS + k0)) * F3D + DD + h * HD;
            #pragma unroll
            for (int j = 0; j < 8; j++) {
                int lin = j * 256 + tid;
                int row = lin >> 5, d = (lin & 31) * 4;
                float4 v = *(const float4*)(kbase + (size_t)row * F3D + d);
                unsigned hxy = pack_h2(v.x, v.y), hzw = pack_h2(v.z, v.w);
                __half2 hh0 = *(__half2*)&hxy, hh1 = *(__half2*)&hzw;
                float2 f0 = __half22float2(hh0), f1 = __half22float2(hh1);
                Kh2[row * KST + d / 2]     = hxy;
                Kh2[row * KST + d / 2 + 1] = hzw;
                Kl2[row * KST + d / 2]     = pack_h2(v.x - f0.x, v.y - f0.y);
                Kl2[row * KST + d / 2 + 1] = pack_h2(v.z - f1.x, v.w - f1.y);
            }
            const float* vbase = qkv + ((size_t)(b * SS + k0)) * F3D + 2 * DD + h * HD;
            #pragma unroll
            for (int j = 0; j < 4; j++) {
                int id = j * 256 + tid;
                int key2 = id >> 5, d = (id & 31) * 4;
                const float* p0 = vbase + (size_t)(2 * key2) * F3D + d;
                float4 va = *(const float4*)p0;
                float4 vb = *(const float4*)(p0 + F3D);
                Vt[(d + 0) * VST2 + key2] = pack_h2(va.x, vb.x);
                Vt[(d + 1) * VST2 + key2] = pack_h2(va.y, vb.y);
                Vt[(d + 2) * VST2 + key2] = pack_h2(va.z, vb.z);
                Vt[(d + 3) * VST2 + key2] = pack_h2(va.w, vb.w);
            }
        }
        __syncthreads();

        // ---- S = Q K^T : 3-term fp16 ----
        float s[8][4];
        #pragma unroll
        for (int nf = 0; nf < 8; nf++)
            #pragma unroll
            for (int j = 0; j < 4; j++) s[nf][j] = 0.f;

        #pragma unroll
        for (int ks = 0; ks < 8; ks++) {
            unsigned ah[4], al[4];
            ldsm_x4(ah[0], ah[1], ah[2], ah[3], uQh + qOff + ks * 32);
            ldsm_x4(al[0], al[1], al[2], al[3], uQl + qOff + ks * 32);
            #pragma unroll
            for (int nfp = 0; nfp < 4; nfp++) {
                unsigned h0, h1, h2, h3, g0, g1, g2, g3;
                ldsm_x4(h0, h1, h2, h3, uKh + kOff[nfp] + ks * 32);
                ldsm_x4(g0, g1, g2, g3, uKl + kOff[nfp] + ks * 32);
                unsigned bh0[2] = {h0, h1}, bh1[2] = {h2, h3};
                unsigned bl0[2] = {g0, g1}, bl1[2] = {g2, g3};
                mma_f16(s[2*nfp],   ah, bh0);
                mma_f16(s[2*nfp],   ah, bl0);
                mma_f16(s[2*nfp],   al, bh0);
                mma_f16(s[2*nfp+1], ah, bh1);
                mma_f16(s[2*nfp+1], ah, bl1);
                mma_f16(s[2*nfp+1], al, bh1);
            }
        }

        // ---- scale + causal mask ----
        #pragma unroll
        for (int nf = 0; nf < 8; nf++) {
            int c0 = k0 + nf * 8 + lc * 2;
            s[nf][0] = (c0     > gr0)     ? -INFINITY : s[nf][0] * scale;
            s[nf][1] = (c0 + 1 > gr0)     ? -INFINITY : s[nf][1] * scale;
            s[nf][2] = (c0     > gr0 + 8) ? -INFINITY : s[nf][2] * scale;
            s[nf][3] = (c0 + 1 > gr0 + 8) ? -INFINITY : s[nf][3] * scale;
        }

        // ---- online softmax ----
        float mn0 = m0, mn1 = m1;
        #pragma unroll
        for (int nf = 0; nf < 8; nf++) {
            mn0 = fmaxf(mn0, fmaxf(s[nf][0], s[nf][1]));
            mn1 = fmaxf(mn1, fmaxf(s[nf][2], s[nf][3]));
        }
        mn0 = fmaxf(mn0, __shfl_xor_sync(0xffffffffu, mn0, 1));
        mn0 = fmaxf(mn0, __shfl_xor_sync(0xffffffffu, mn0, 2));
        mn1 = fmaxf(mn1, __shfl_xor_sync(0xffffffffu, mn1, 1));
        mn1 = fmaxf(mn1, __shfl_xor_sync(0xffffffffu, mn1, 2));

        float corr0 = __expf(m0 - mn0), corr1 = __expf(m1 - mn1);
        m0 = mn0; m1 = mn1;

        float ps0 = 0.f, ps1 = 0.f;
        int r = wrow + lr;
        #pragma unroll
        for (int nf = 0; nf < 8; nf++) {
            float p0 = __expf(s[nf][0] - mn0);
            float p1 = __expf(s[nf][1] - mn0);
            float p2 = __expf(s[nf][2] - mn1);
            float p3 = __expf(s[nf][3] - mn1);
            ps0 += p0 + p1; ps1 += p2 + p3;
            int key2 = nf * 4 + lc;
            Pp[r * PST + key2]       = pack_h2(p0, p1);
            Pp[(r + 8) * PST + key2] = pack_h2(p2, p3);
        }
        ps0 += __shfl_xor_sync(0xffffffffu, ps0, 1);
        ps0 += __shfl_xor_sync(0xffffffffu, ps0, 2);
        ps1 += __shfl_xor_sync(0xffffffffu, ps1, 1);
        ps1 += __shfl_xor_sync(0xffffffffu, ps1, 2);
        l0 = l0 * corr0 + ps0;
        l1 = l1 * corr1 + ps1;

        #pragma unroll
        for (int nf = 0; nf < 16; nf++) {
            o[nf][0] *= corr0; o[nf][1] *= corr0;
            o[nf][2] *= corr1; o[nf][3] *= corr1;
        }
        __syncwarp();

        // ---- O += P V (fp16, ldmatrix) ----
        #pragma unroll
        for (int ks = 0; ks < 4; ks++) {
            unsigned a4[4];
            ldsm_x4(a4[0], a4[1], a4[2], a4[3], uPp + pOff + ks * 32);
            #pragma unroll
            for (int nfp = 0; nfp < 8; nfp++) {
                unsigned q0, q1, q2, q3;
                ldsm_x4(q0, q1, q2, q3, uVt + vOff[nfp] + ks * 32);
                unsigned b0[2] = {q0, q1}, b1[2] = {q2, q3};
                mma_f16(o[2*nfp],   a4, b0);
                mma_f16(o[2*nfp+1], a4, b1);
            }
        }
        __syncwarp();
    }

    // ---- epilogue ----
    float il0 = 1.f / l0, il1 = 1.f / l1;
    float ss0 = 0.f, ss1 = 0.f;
    #pragma unroll
    for (int nf = 0; nf < 16; nf++) {
        o[nf][0] *= il0; o[nf][1] *= il0;
        o[nf][2] *= il1; o[nf][3] *= il1;
        ss0 += o[nf][0]*o[nf][0] + o[nf][1]*o[nf][1];
        ss1 += o[nf][2]*o[nf][2] + o[nf][3]*o[nf][3];
    }
    ss0 += __shfl_xor_sync(0xffffffffu, ss0, 1);
    ss0 += __shfl_xor_sync(0xffffffffu, ss0, 2);
    ss1 += __shfl_xor_sync(0xffffffffu, ss1, 1);
    ss1 += __shfl_xor_sync(0xffffffffu, ss1, 2);
    float rn0 = rsqrtf(ss0 * (1.f / HD) + 1e-6f);
    float rn1 = rsqrtf(ss1 * (1.f / HD) + 1e-6f);

    __half* o0 = out + ((size_t)(b * SS + gr0)) * DD + h * HD;
    __half* o1 = out + ((size_t)(b * SS + gr0 + 8)) * DD + h * HD;
    #pragma unroll
    for (int nf = 0; nf < 16; nf++) {
        int col = nf * 8 + lc * 2;
        *(unsigned*)(o0 + col) = pack_h2(o[nf][0] * rn0, o[nf][1] * rn0);
        *(unsigned*)(o1 + col) = pack_h2(o[nf][2] * rn1, o[nf][3] * rn1);
    }
}

// ---------------------------------------------------------------------------
extern "C" void kernel_launch(void* const* d_in, const int* in_sizes, int n_in,
                              void* d_out, int out_size)
{
    const float* x = nullptr; const float* w_in = nullptr; const float* w_out = nullptr;
    for (int i = 0; i < n_in; i++) {
        if (in_sizes[i] == BB * SS * DD)      x     = (const float*)d_in[i];
        else if (in_sizes[i] == F3D * DD)     w_in  = (const float*)d_in[i];
        else if (in_sizes[i] == DD * DD)      w_out = (const float*)d_in[i];
    }

    __half* xh;     cudaGetSymbolAddress((void**)&xh, g_xh);
    __half* win_h;  cudaGetSymbolAddress((void**)&win_h, g_win_h);
    __half* wout_h; cudaGetSymbolAddress((void**)&wout_h, g_wout_h);
    float*  qkv;    cudaGetSymbolAddress((void**)&qkv, g_qkv);
    __half* ah;     cudaGetSymbolAddress((void**)&ah, g_ah);

    cudaFuncSetAttribute(gemm_fp16, cudaFuncAttributeMaxDynamicSharedMemorySize, GEMM_SMEM);
    cudaFuncSetAttribute(flash_attn_fp16, cudaFuncAttributeMaxDynamicSharedMemorySize, ATT_SMEM);

    cvt_f2h<<<(MROWS * DD) / 1024, 256>>>(x, xh);
    unit_norm_rows_h<<<F3D, 256>>>(w_in, win_h, DD);
    unit_norm_rows_h<<<DD, 256>>>(w_out, wout_h, DD);

    {
        dim3 grid(F3D / 128, MROWS / 128);
        gemm_fp16<<<grid, 256, GEMM_SMEM>>>(xh, win_h, qkv, MROWS, F3D, DD);
    }
    {
        int totalWarps = BB * SS * HH * 2;
        int blocks = (totalWarps * 32 + 255) / 256;
        rmsnorm_qk<<<blocks, 256>>>(qkv);
    }
    {
        dim3 grid(SS / 128, HH, BB);
        flash_attn_fp16<<<grid, 256, ATT_SMEM>>>(qkv, ah);
    }
    {
        dim3 grid(DD / 128, MROWS / 128);
        gemm_fp16<<<grid, 256, GEMM_SMEM>>>(ah, wout_h, (float*)d_out, MROWS, DD, DD);
    }
}

// round 10
// speedup vs baseline: 17.9628x; 1.1133x over previous
#include <cuda_runtime.h>
#include <cuda_fp16.h>
#include <math.h>
#include <cstdint>

// Problem constants
#define BB 4
#define SS 2048
#define DD 2048
#define HH 16
#define HD 128
#define F3D (3*DD)          // 6144
#define MROWS (BB*SS)       // 8192

// Scratch (device globals; no allocation allowed)
__device__ __half g_xh[(size_t)MROWS * DD];
__device__ __half g_win_h[(size_t)F3D * DD];
__device__ __half g_wout_h[(size_t)DD * DD];
__device__ float  g_qkv[(size_t)MROWS * F3D];
__device__ __half g_qh[(size_t)MROWS * DD];   // rms-normed q, hi half
__device__ __half g_ql[(size_t)MROWS * DD];   // lo residual
__device__ __half g_kh[(size_t)MROWS * DD];
__device__ __half g_kl[(size_t)MROWS * DD];
__device__ unsigned g_vt[(size_t)BB * HH * HD * (SS/2)];  // half2(v[2k][d],v[2k+1][d])
__device__ __half g_ah[(size_t)MROWS * DD];

extern __shared__ __align__(16) char dyn_smem[];

// ---------------------------------------------------------------------------
__device__ __forceinline__ uint32_t smem_to_u32(const void* p) {
    uint32_t a;
    asm("{ .reg .u64 t; cvta.to.shared.u64 t, %1; cvt.u32.u64 %0, t; }" : "=r"(a) : "l"(p));
    return a;
}
__device__ __forceinline__ void cp_async16(uint32_t saddr, const void* gptr) {
    asm volatile("cp.async.cg.shared.global [%0], [%1], 16;" :: "r"(saddr), "l"(gptr));
}
#define CP_COMMIT() asm volatile("cp.async.commit_group;" ::: "memory")
#define CP_WAIT1()  asm volatile("cp.async.wait_group 1;" ::: "memory")
#define CP_WAIT0()  asm volatile("cp.async.wait_group 0;" ::: "memory")

__device__ __forceinline__ void mma_f16(float* c, const unsigned* a, const unsigned* b) {
    asm volatile(
        "mma.sync.aligned.m16n8k16.row.col.f32.f16.f16.f32 "
        "{%0,%1,%2,%3}, {%4,%5,%6,%7}, {%8,%9}, {%0,%1,%2,%3};"
        : "+f"(c[0]), "+f"(c[1]), "+f"(c[2]), "+f"(c[3])
        : "r"(a[0]), "r"(a[1]), "r"(a[2]), "r"(a[3]), "r"(b[0]), "r"(b[1]));
}
__device__ __forceinline__ void ldsm_x4(unsigned& r0, unsigned& r1, unsigned& r2,
                                        unsigned& r3, uint32_t addr) {
    asm volatile("ldmatrix.sync.aligned.m8n8.x4.shared.b16 {%0,%1,%2,%3}, [%4];"
        : "=r"(r0), "=r"(r1), "=r"(r2), "=r"(r3) : "r"(addr));
}
__device__ __forceinline__ unsigned pack_h2(float lo, float hi) {
    __half2 h = __floats2half2_rn(lo, hi);
    return *(unsigned*)&h;
}

// ---------------------------------------------------------------------------
__global__ void __launch_bounds__(256) cvt_f2h(const float* __restrict__ x,
                                               __half* __restrict__ xh)
{
    size_t i = ((size_t)blockIdx.x * 256 + threadIdx.x) * 4;
    float4 v = *(const float4*)(x + i);
    unsigned* o = (unsigned*)(xh + i);
    o[0] = pack_h2(v.x, v.y);
    o[1] = pack_h2(v.z, v.w);
}

// ---------------------------------------------------------------------------
__global__ void __launch_bounds__(256) unit_norm_rows_h(
    const float* __restrict__ w, __half* __restrict__ o, int cols)
{
    int row = blockIdx.x, tid = threadIdx.x;
    const float* src = w + (size_t)row * cols;
    __half* dst = o + (size_t)row * cols;
    float ss = 0.f;
    for (int i = tid * 4; i < cols; i += 1024) {
        float4 v = *(const float4*)(src + i);
        ss += v.x*v.x + v.y*v.y + v.z*v.z + v.w*v.w;
    }
    #pragma unroll
    for (int off = 16; off; off >>= 1) ss += __shfl_xor_sync(0xffffffffu, ss, off);
    __shared__ float red[8];
    if ((tid & 31) == 0) red[tid >> 5] = ss;
    __syncthreads();
    float total = 0.f;
    #pragma unroll
    for (int i = 0; i < 8; i++) total += red[i];
    float r = rsqrtf(total + 1e-6f);
    for (int i = tid * 4; i < cols; i += 1024) {
        float4 v = *(const float4*)(src + i);
        unsigned* op = (unsigned*)(dst + i);
        op[0] = pack_h2(v.x * r, v.y * r);
        op[1] = pack_h2(v.z * r, v.w * r);
    }
}

// ---------------------------------------------------------------------------
// FP16 GEMM, 3-stage cp.async pipeline + ldmatrix (unchanged from round 9).
// ---------------------------------------------------------------------------
#define HBKP 40
#define HSTG_B 20480
#define GEMM_SMEM (3 * HSTG_B)

__global__ void __launch_bounds__(256, 2) gemm_fp16(
    const __half* __restrict__ A, const __half* __restrict__ B,
    float* __restrict__ C, int M, int N, int K)
{
    __half* smem = (__half*)dyn_smem;

    int tid = threadIdx.x, lane = tid & 31, warp = tid >> 5;
    int wm = warp >> 2, wn = warp & 3;
    int mBase = blockIdx.y * 128, nBase = blockIdx.x * 128;
    int lr = lane >> 2, lc = lane & 3;
    int l7 = lane & 7, l8 = (lane >> 3) & 1, l16 = lane >> 4;

    int r0 = tid >> 2, o0 = (tid & 3) * 8;
    const __half* Ap0 = A + (size_t)(mBase + r0) * K + o0;
    const __half* Ap1 = A + (size_t)(mBase + r0 + 64) * K + o0;
    const __half* Bp0 = B + (size_t)(nBase + r0) * K + o0;
    const __half* Bp1 = B + (size_t)(nBase + r0 + 64) * K + o0;

    uint32_t sb = smem_to_u32(smem);
    uint32_t sA0 = sb + (r0 * HBKP + o0) * 2;
    uint32_t sA1 = sb + ((r0 + 64) * HBKP + o0) * 2;
    uint32_t sB0 = sA0 + 128 * HBKP * 2;
    uint32_t sB1 = sA1 + 128 * HBKP * 2;

    uint32_t aOff[4], bOff[2];
    #pragma unroll
    for (int mf = 0; mf < 4; mf++)
        aOff[mf] = ((wm * 64 + mf * 16 + l7 + l8 * 8) * HBKP + l16 * 8) * 2;
    #pragma unroll
    for (int nfp = 0; nfp < 2; nfp++)
        bOff[nfp] = ((wn * 32 + nfp * 16 + l16 * 8 + l7) * HBKP + l8 * 8) * 2;

    float acc[4][4][4];
    #pragma unroll
    for (int i = 0; i < 4; i++)
        #pragma unroll
        for (int j = 0; j < 4; j++)
            #pragma unroll
            for (int l = 0; l < 4; l++) acc[i][j][l] = 0.f;

    const int T = K / 32;

    #pragma unroll
    for (int s = 0; s < 2; s++) {
        uint32_t so = s * HSTG_B;
        int k0 = s * 32;
        cp_async16(sA0 + so, Ap0 + k0);
        cp_async16(sA1 + so, Ap1 + k0);
        cp_async16(sB0 + so, Bp0 + k0);
        cp_async16(sB1 + so, Bp1 + k0);
        CP_COMMIT();
    }

    for (int t = 0; t < T; t++) {
        CP_WAIT1();
        __syncthreads();

        if (t + 2 < T) {
            uint32_t so = ((t + 2) % 3) * HSTG_B;
            int k0 = (t + 2) * 32;
            cp_async16(sA0 + so, Ap0 + k0);
            cp_async16(sA1 + so, Ap1 + k0);
            cp_async16(sB0 + so, Bp0 + k0);
            cp_async16(sB1 + so, Bp1 + k0);
        }
        CP_COMMIT();

        uint32_t sS = sb + (t % 3) * HSTG_B;
        uint32_t sBB = sS + 128 * HBKP * 2;
        #pragma unroll
        for (int ch = 0; ch < 2; ch++) {
            uint32_t cB = ch * 32;
            unsigned a[4][4], b[4][2];
            #pragma unroll
            for (int mf = 0; mf < 4; mf++)
                ldsm_x4(a[mf][0], a[mf][1], a[mf][2], a[mf][3], sS + aOff[mf] + cB);
            #pragma unroll
            for (int nfp = 0; nfp < 2; nfp++) {
                unsigned q0, q1, q2, q3;
                ldsm_x4(q0, q1, q2, q3, sBB + bOff[nfp] + cB);
                b[2*nfp][0] = q0; b[2*nfp][1] = q1;
                b[2*nfp+1][0] = q2; b[2*nfp+1][1] = q3;
            }
            #pragma unroll
            for (int mf = 0; mf < 4; mf++)
                #pragma unroll
                for (int nf = 0; nf < 4; nf++)
                    mma_f16(acc[mf][nf], a[mf], b[nf]);
        }
    }

    #pragma unroll
    for (int mf = 0; mf < 4; mf++) {
        int row = mBase + wm * 64 + mf * 16 + lr;
        #pragma unroll
        for (int nf = 0; nf < 4; nf++) {
            int col = nBase + wn * 32 + nf * 8 + lc * 2;
            float2 v0 = {acc[mf][nf][0], acc[mf][nf][1]};
            float2 v1 = {acc[mf][nf][2], acc[mf][nf][3]};
            *(float2*)(C + (size_t)row * N + col)       = v0;
            *(float2*)(C + (size_t)(row + 8) * N + col) = v1;
        }
    }
}

// ---------------------------------------------------------------------------
// prep_qk: rms_norm q,k rows + split into (hi,lo) fp16 globals. 1 warp/row.
// ---------------------------------------------------------------------------
__global__ void __launch_bounds__(256) prep_qk(
    const float* __restrict__ qkv,
    __half* __restrict__ qh, __half* __restrict__ ql,
    __half* __restrict__ kh, __half* __restrict__ kl)
{
    int gw = (blockIdx.x * blockDim.x + threadIdx.x) >> 5;
    int lane = threadIdx.x & 31;
    int which = gw & 1;
    int t = gw >> 1;
    int h = t % HH;
    int bs = t / HH;
    const float* p = qkv + (size_t)bs * F3D + which * DD + h * HD + lane * 4;
    float4 v = *(const float4*)p;
    float ss = v.x*v.x + v.y*v.y + v.z*v.z + v.w*v.w;
    #pragma unroll
    for (int off = 16; off; off >>= 1) ss += __shfl_xor_sync(0xffffffffu, ss, off);
    float r = rsqrtf(ss * (1.f / HD) + 1e-6f);
    v.x *= r; v.y *= r; v.z *= r; v.w *= r;

    size_t oidx = (size_t)bs * DD + h * HD + lane * 4;
    __half* oh = (which ? kh : qh) + oidx;
    __half* ol = (which ? kl : ql) + oidx;
    unsigned hxy = pack_h2(v.x, v.y), hzw = pack_h2(v.z, v.w);
    __half2 hh0 = *(__half2*)&hxy, hh1 = *(__half2*)&hzw;
    float2 f0 = __half22float2(hh0), f1 = __half22float2(hh1);
    uint2 hi = {hxy, hzw};
    uint2 lo = {pack_h2(v.x - f0.x, v.y - f0.y), pack_h2(v.z - f1.x, v.w - f1.y)};
    *(uint2*)oh = hi;
    *(uint2*)ol = lo;
}

// ---------------------------------------------------------------------------
// vprep: pack V into transposed key-pair half2 layout [b,h,d,key2].
// ---------------------------------------------------------------------------
__global__ void __launch_bounds__(256) vprep(
    const float* __restrict__ qkv, unsigned* __restrict__ vt)
{
    int id = blockIdx.x * 256 + threadIdx.x;
    int lane = id & 31;
    int idx = id >> 5;
    int d4 = idx & 31;
    int k2b = (idx >> 5) & 31;
    int bh = idx >> 10;              // 0..63
    int b = bh >> 4, h = bh & 15;
    int key2 = k2b * 32 + lane;

    const float* p0 = qkv + ((size_t)(b * SS + 2 * key2)) * F3D + 2 * DD + h * HD + d4 * 4;
    float4 va = *(const float4*)p0;
    float4 vb = *(const float4*)(p0 + F3D);
    size_t base = ((size_t)bh * HD + d4 * 4) * (SS / 2) + key2;
    vt[base]                = pack_h2(va.x, vb.x);
    vt[base + (SS/2)]       = pack_h2(va.y, vb.y);
    vt[base + 2*(SS/2)]     = pack_h2(va.z, vb.z);
    vt[base + 3*(SS/2)]     = pack_h2(va.w, vb.w);
}

// ---------------------------------------------------------------------------
// FP16 flash attention: pure cp.async staging, 2-stage KV ring, ldmatrix.
// smem (uints): Qh[128*68] Ql[128*68] | stage s in {0,1}: Kh[64*68] Kl[64*68]
//               Vt[128*36] | Pp[128*36]
// ---------------------------------------------------------------------------
#define QST 68
#define KST 68
#define VST2 36
#define PST 36
#define KVU (64*KST*2 + 128*VST2)          // 13312 uints per stage
#define ATT_SMEM ((128*QST*2 + 2*KVU + 128*PST) * 4)

__global__ void __launch_bounds__(256) flash_attn_fp16(
    const __half* __restrict__ qh, const __half* __restrict__ ql,
    const __half* __restrict__ kh, const __half* __restrict__ kl,
    const unsigned* __restrict__ vt, __half* __restrict__ out)
{
    uint32_t sbase = smem_to_u32(dyn_smem);
    uint32_t uQh = sbase;
    uint32_t uQl = sbase + 8704u * 4;
    uint32_t uKV0 = sbase + 17408u * 4;
    uint32_t uPp = sbase + (17408u + 2 * KVU) * 4;
    unsigned* Pp = (unsigned*)dyn_smem + 17408 + 2 * KVU;

    int tid = threadIdx.x, lane = tid & 31, wid = tid >> 5;
    int lr = lane >> 2, lc = lane & 3;
    int l7 = lane & 7, l8 = (lane >> 3) & 1, l16 = lane >> 4;
    int b = blockIdx.z, h = blockIdx.y;
    int qb = (int)gridDim.x - 1 - (int)blockIdx.x;
    int wrow = wid * 16;
    int bh = b * HH + h;

    uint32_t qOff = ((wrow + l7 + l8 * 8) * QST + l16 * 4) * 4;
    uint32_t pOff = ((wrow + l7 + l8 * 8) * PST + l16 * 4) * 4;
    uint32_t kOff[4], vOff[8];
    #pragma unroll
    for (int nfp = 0; nfp < 4; nfp++)
        kOff[nfp] = ((nfp * 16 + l16 * 8 + l7) * KST + l8 * 4) * 4;
    #pragma unroll
    for (int nfp = 0; nfp < 8; nfp++)
        vOff[nfp] = (8704u + (nfp * 16 + l16 * 8 + l7) * VST2 + l8 * 4) * 4;

    const float scale = 0.08838834764831845f;

    // staging lambdas (inlined manually)
    // Q: 128 rows x 16 chunks, both hi/lo -> 16 chunks/thread
    {
        const __half* qhb = qh + ((size_t)(b * SS + qb * 128)) * DD + h * HD;
        const __half* qlb = ql + ((size_t)(b * SS + qb * 128)) * DD + h * HD;
        #pragma unroll
        for (int j = 0; j < 8; j++) {
            int lin = j * 256 + tid;
            int row = lin >> 4, ch = lin & 15;
            uint32_t d = (row * QST + ch * 4) * 4;
            cp_async16(uQh + d, qhb + (size_t)row * DD + ch * 8);
            cp_async16(uQl + d, qlb + (size_t)row * DD + ch * 8);
        }
    }

    int nIter = 2 * (qb + 1);
    const __half* khb = kh + (size_t)(b * SS) * DD + h * HD;
    const __half* klb = kl + (size_t)(b * SS) * DD + h * HD;
    const unsigned* vtb = vt + (size_t)bh * HD * (SS / 2);

    // issue KV tile 0 into stage 0 (same group as Q)
    {
        #pragma unroll
        for (int j = 0; j < 4; j++) {
            int lin = j * 256 + tid;
            int row = lin >> 4, ch = lin & 15;
            uint32_t d = uKV0 + (row * KST + ch * 4) * 4;
            cp_async16(d, khb + (size_t)row * DD + ch * 8);
            cp_async16(d + 4352u * 4, klb + (size_t)row * DD + ch * 8);
        }
        #pragma unroll
        for (int j = 0; j < 4; j++) {
            int lin = j * 256 + tid;
            int dd = lin >> 3, ch = lin & 7;
            cp_async16(uKV0 + (8704u + dd * VST2 + ch * 4) * 4,
                       vtb + (size_t)dd * (SS / 2) + ch * 4);
        }
        CP_COMMIT();
    }

    float o[16][4];
    #pragma unroll
    for (int i = 0; i < 16; i++)
        #pragma unroll
        for (int j = 0; j < 4; j++) o[i][j] = 0.f;
    float m0 = -INFINITY, m1 = -INFINITY, l0 = 0.f, l1 = 0.f;

    int gr0 = qb * 128 + wrow + lr;

    for (int t = 0; t < nIter; t++) {
        int k0 = t * 64;
        uint32_t uS = uKV0 + (uint32_t)(t & 1) * (KVU * 4);

        // issue next tile into other stage
        if (t + 1 < nIter) {
            uint32_t uN = uKV0 + (uint32_t)((t + 1) & 1) * (KVU * 4);
            int kn = (t + 1) * 64;
            #pragma unroll
            for (int j = 0; j < 4; j++) {
                int lin = j * 256 + tid;
                int row = lin >> 4, ch = lin & 15;
                uint32_t d = uN + (row * KST + ch * 4) * 4;
                cp_async16(d, khb + (size_t)(kn + row) * DD + ch * 8);
                cp_async16(d + 4352u * 4, klb + (size_t)(kn + row) * DD + ch * 8);
            }
            #pragma unroll
            for (int j = 0; j < 4; j++) {
                int lin = j * 256 + tid;
                int dd = lin >> 3, ch = lin & 7;
                cp_async16(uN + (8704u + dd * VST2 + ch * 4) * 4,
                           vtb + (size_t)dd * (SS / 2) + kn / 2 + ch * 4);
            }
            CP_COMMIT();
            CP_WAIT1();
        } else {
            CP_WAIT0();
        }
        __syncthreads();    // tile t visible to all warps

        // ---- S = Q K^T : 3-term fp16 ----
        float s[8][4];
        #pragma unroll
        for (int nf = 0; nf < 8; nf++)
            #pragma unroll
            for (int j = 0; j < 4; j++) s[nf][j] = 0.f;

        #pragma unroll
        for (int ks = 0; ks < 8; ks++) {
            unsigned ah[4], al[4];
            ldsm_x4(ah[0], ah[1], ah[2], ah[3], uQh + qOff + ks * 32);
            ldsm_x4(al[0], al[1], al[2], al[3], uQl + qOff + ks * 32);
            #pragma unroll
            for (int nfp = 0; nfp < 4; nfp++) {
                unsigned h0, h1, h2, h3, g0, g1, g2, g3;
                ldsm_x4(h0, h1, h2, h3, uS + kOff[nfp] + ks * 32);
                ldsm_x4(g0, g1, g2, g3, uS + 4352u * 4 + kOff[nfp] + ks * 32);
                unsigned bh0[2] = {h0, h1}, bh1[2] = {h2, h3};
                unsigned bl0[2] = {g0, g1}, bl1[2] = {g2, g3};
                mma_f16(s[2*nfp],   ah, bh0);
                mma_f16(s[2*nfp],   ah, bl0);
                mma_f16(s[2*nfp],   al, bh0);
                mma_f16(s[2*nfp+1], ah, bh1);
                mma_f16(s[2*nfp+1], ah, bl1);
                mma_f16(s[2*nfp+1], al, bh1);
            }
        }

        // ---- scale + causal mask ----
        #pragma unroll
        for (int nf = 0; nf < 8; nf++) {
            int c0 = k0 + nf * 8 + lc * 2;
            s[nf][0] = (c0     > gr0)     ? -INFINITY : s[nf][0] * scale;
            s[nf][1] = (c0 + 1 > gr0)     ? -INFINITY : s[nf][1] * scale;
            s[nf][2] = (c0     > gr0 + 8) ? -INFINITY : s[nf][2] * scale;
            s[nf][3] = (c0 + 1 > gr0 + 8) ? -INFINITY : s[nf][3] * scale;
        }

        // ---- online softmax ----
        float mn0 = m0, mn1 = m1;
        #pragma unroll
        for (int nf = 0; nf < 8; nf++) {
            mn0 = fmaxf(mn0, fmaxf(s[nf][0], s[nf][1]));
            mn1 = fmaxf(mn1, fmaxf(s[nf][2], s[nf][3]));
        }
        mn0 = fmaxf(mn0, __shfl_xor_sync(0xffffffffu, mn0, 1));
        mn0 = fmaxf(mn0, __shfl_xor_sync(0xffffffffu, mn0, 2));
        mn1 = fmaxf(mn1, __shfl_xor_sync(0xffffffffu, mn1, 1));
        mn1 = fmaxf(mn1, __shfl_xor_sync(0xffffffffu, mn1, 2));

        float corr0 = __expf(m0 - mn0), corr1 = __expf(m1 - mn1);
        m0 = mn0; m1 = mn1;

        float ps0 = 0.f, ps1 = 0.f;
        int r = wrow + lr;
        #pragma unroll
        for (int nf = 0; nf < 8; nf++) {
            float p0 = __expf(s[nf][0] - mn0);
            float p1 = __expf(s[nf][1] - mn0);
            float p2 = __expf(s[nf][2] - mn1);
            float p3 = __expf(s[nf][3] - mn1);
            ps0 += p0 + p1; ps1 += p2 + p3;
            int key2 = nf * 4 + lc;
            Pp[r * PST + key2]       = pack_h2(p0, p1);
            Pp[(r + 8) * PST + key2] = pack_h2(p2, p3);
        }
        ps0 += __shfl_xor_sync(0xffffffffu, ps0, 1);
        ps0 += __shfl_xor_sync(0xffffffffu, ps0, 2);
        ps1 += __shfl_xor_sync(0xffffffffu, ps1, 1);
        ps1 += __shfl_xor_sync(0xffffffffu, ps1, 2);
        l0 = l0 * corr0 + ps0;
        l1 = l1 * corr1 + ps1;

        #pragma unroll
        for (int nf = 0; nf < 16; nf++) {
            o[nf][0] *= corr0; o[nf][1] *= corr0;
            o[nf][2] *= corr1; o[nf][3] *= corr1;
        }
        __syncwarp();

        // ---- O += P V (fp16, ldmatrix) ----
        #pragma unroll
        for (int ks = 0; ks < 4; ks++) {
            unsigned a4[4];
            ldsm_x4(a4[0], a4[1], a4[2], a4[3], uPp + pOff + ks * 32);
            #pragma unroll
            for (int nfp = 0; nfp < 8; nfp++) {
                unsigned q0, q1, q2, q3;
                ldsm_x4(q0, q1, q2, q3, uS + vOff[nfp] + ks * 32);
                unsigned b0[2] = {q0, q1}, b1[2] = {q2, q3};
                mma_f16(o[2*nfp],   a4, b0);
                mma_f16(o[2*nfp+1], a4, b1);
            }
        }
        __syncthreads();    // all reads of stage t done -> safe to overwrite
    }

    // ---- epilogue ----
    float il0 = 1.f / l0, il1 = 1.f / l1;
    float ss0 = 0.f, ss1 = 0.f;
    #pragma unroll
    for (int nf = 0; nf < 16; nf++) {
        o[nf][0] *= il0; o[nf][1] *= il0;
        o[nf][2] *= il1; o[nf][3] *= il1;
        ss0 += o[nf][0]*o[nf][0] + o[nf][1]*o[nf][1];
        ss1 += o[nf][2]*o[nf][2] + o[nf][3]*o[nf][3];
    }
    ss0 += __shfl_xor_sync(0xffffffffu, ss0, 1);
    ss0 += __shfl_xor_sync(0xffffffffu, ss0, 2);
    ss1 += __shfl_xor_sync(0xffffffffu, ss1, 1);
    ss1 += __shfl_xor_sync(0xffffffffu, ss1, 2);
    float rn0 = rsqrtf(ss0 * (1.f / HD) + 1e-6f);
    float rn1 = rsqrtf(ss1 * (1.f / HD) + 1e-6f);

    __half* o0 = out + ((size_t)(b * SS + gr0)) * DD + h * HD;
    __half* o1 = out + ((size_t)(b * SS + gr0 + 8)) * DD + h * HD;
    #pragma unroll
    for (int nf = 0; nf < 16; nf++) {
        int col = nf * 8 + lc * 2;
        *(unsigned*)(o0 + col) = pack_h2(o[nf][0] * rn0, o[nf][1] * rn0);
        *(unsigned*)(o1 + col) = pack_h2(o[nf][2] * rn1, o[nf][3] * rn1);
    }
}

// ---------------------------------------------------------------------------
extern "C" void kernel_launch(void* const* d_in, const int* in_sizes, int n_in,
                              void* d_out, int out_size)
{
    const float* x = nullptr; const float* w_in = nullptr; const float* w_out = nullptr;
    for (int i = 0; i < n_in; i++) {
        if (in_sizes[i] == BB * SS * DD)      x     = (const float*)d_in[i];
        else if (in_sizes[i] == F3D * DD)     w_in  = (const float*)d_in[i];
        else if (in_sizes[i] == DD * DD)      w_out = (const float*)d_in[i];
    }

    __half* xh;     cudaGetSymbolAddress((void**)&xh, g_xh);
    __half* win_h;  cudaGetSymbolAddress((void**)&win_h, g_win_h);
    __half* wout_h; cudaGetSymbolAddress((void**)&wout_h, g_wout_h);
    float*  qkv;    cudaGetSymbolAddress((void**)&qkv, g_qkv);
    __half* qh;     cudaGetSymbolAddress((void**)&qh, g_qh);
    __half* ql;     cudaGetSymbolAddress((void**)&ql, g_ql);
    __half* kh;     cudaGetSymbolAddress((void**)&kh, g_kh);
    __half* kl;     cudaGetSymbolAddress((void**)&kl, g_kl);
    unsigned* vt;   cudaGetSymbolAddress((void**)&vt, g_vt);
    __half* ah;     cudaGetSymbolAddress((void**)&ah, g_ah);

    cudaFuncSetAttribute(gemm_fp16, cudaFuncAttributeMaxDynamicSharedMemorySize, GEMM_SMEM);
    cudaFuncSetAttribute(flash_attn_fp16, cudaFuncAttributeMaxDynamicSharedMemorySize, ATT_SMEM);

    cvt_f2h<<<(MROWS * DD) / 1024, 256>>>(x, xh);
    unit_norm_rows_h<<<F3D, 256>>>(w_in, win_h, DD);
    unit_norm_rows_h<<<DD, 256>>>(w_out, wout_h, DD);

    {
        dim3 grid(F3D / 128, MROWS / 128);
        gemm_fp16<<<grid, 256, GEMM_SMEM>>>(xh, win_h, qkv, MROWS, F3D, DD);
    }
    {
        // rms_norm + hi/lo split for q,k: 8192*2*16 warps
        int blocks = (MROWS * 2 * HH) * 32 / 256;
        prep_qk<<<blocks, 256>>>(qkv, qh, ql, kh, kl);
        // v pack: 64 bh * 32 d4 * 32 k2b * 32 lanes threads
        vprep<<<(BB * HH * 32 * 32 * 32) / 256, 256>>>(qkv, vt);
    }
    {
        dim3 grid(SS / 128, HH, BB);
        flash_attn_fp16<<<grid, 256, ATT_SMEM>>>(qh, ql, kh, kl, vt, ah);
    }
    {
        dim3 grid(DD / 128, MROWS / 128);
        gemm_fp16<<<grid, 256, GEMM_SMEM>>>(ah, wout_h, (float*)d_out, MROWS, DD, DD);
    }
}